// round 1
// baseline (speedup 1.0000x reference)
#include <cuda_runtime.h>

#define L_SEQ  2048
#define BATCH  2
#define DMODEL 1024
#define NHEADS 16
#define DK     64
#define E3     3072           // 3 * DMODEL
#define NROWS  4096           // L_SEQ * BATCH

// Scratch for projected QKV: [NROWS][E3], row r = l*BATCH + b, col e = h*192 + {q:0..63, k:64..127, v:128..191}
__device__ float g_qkv[NROWS * E3];

// theta_j = 10000^(-j/16) = 10^(-j/4), exact fp32-rounded constants
__constant__ float c_theta[16] = {
    1.0f,                     0.5623413251903491f,     0.31622776601683794f,   0.17782794100389228f,
    0.1f,                     0.05623413251903491f,    0.031622776601683794f,  0.017782794100389228f,
    0.01f,                    0.005623413251903491f,   0.0031622776601683794f, 0.0017782794100389228f,
    0.001f,                   0.0005623413251903491f,  0.00031622776601683794f,0.00017782794100389227f
};

// ---------------------------------------------------------------------------
// Kernel 1: QKV projection GEMM.  qkv[r][e] = sum_d X[r][d] * W[e][d]
// 64x64 tile, BK=16, 256 threads, 4x4 micro-tile per thread.
// ---------------------------------------------------------------------------
__global__ void __launch_bounds__(256) qkv_gemm(const float* __restrict__ X,
                                                const float* __restrict__ W) {
    __shared__ __align__(16) float As[16][68];   // As[k][m] (transposed)
    __shared__ __align__(16) float Bs[16][68];   // Bs[k][e] (transposed)

    const int tid = threadIdx.x;
    const int tx  = tid & 15;          // 0..15 -> cols (e)
    const int ty  = tid >> 4;          // 0..15 -> rows (r)
    const int r0  = blockIdx.y * 64;
    const int e0  = blockIdx.x * 64;

    const int lr = tid >> 2;           // 0..63 row within tile (for loads)
    const int lk = (tid & 3) * 4;      // 0,4,8,12 k-group (for loads)

    const float* Ar = X + (r0 + lr) * DMODEL + lk;
    const float* Br = W + (e0 + lr) * DMODEL + lk;

    float acc[4][4] = {};

    for (int k0 = 0; k0 < DMODEL; k0 += 16) {
        float4 a = *reinterpret_cast<const float4*>(Ar + k0);
        float4 b = *reinterpret_cast<const float4*>(Br + k0);
        __syncthreads();
        As[lk + 0][lr] = a.x; As[lk + 1][lr] = a.y; As[lk + 2][lr] = a.z; As[lk + 3][lr] = a.w;
        Bs[lk + 0][lr] = b.x; Bs[lk + 1][lr] = b.y; Bs[lk + 2][lr] = b.z; Bs[lk + 3][lr] = b.w;
        __syncthreads();
#pragma unroll
        for (int kk = 0; kk < 16; kk++) {
            float4 av = *reinterpret_cast<const float4*>(&As[kk][ty * 4]);
            float4 bv = *reinterpret_cast<const float4*>(&Bs[kk][tx * 4]);
            float aa[4] = {av.x, av.y, av.z, av.w};
            float bb[4] = {bv.x, bv.y, bv.z, bv.w};
#pragma unroll
            for (int i = 0; i < 4; i++)
#pragma unroll
                for (int j = 0; j < 4; j++)
                    acc[i][j] += aa[i] * bb[j];
        }
    }

#pragma unroll
    for (int i = 0; i < 4; i++) {
        float4 o = make_float4(acc[i][0], acc[i][1], acc[i][2], acc[i][3]);
        *reinterpret_cast<float4*>(&g_qkv[(r0 + ty * 4 + i) * E3 + e0 + tx * 4]) = o;
    }
}

// ---------------------------------------------------------------------------
// Kernel 2: in-place RoPE on the q and k slices of g_qkv.
// One thread handles one rotation pair (j, j+16).
// Total threads = NROWS * NHEADS * 2 * 16 = 2,097,152 (exact grid).
// ---------------------------------------------------------------------------
__global__ void __launch_bounds__(256) rope_kernel() {
    const int t   = blockIdx.x * 256 + threadIdx.x;
    const int j   = t & 15;
    const int sqk = (t >> 4) & 1;      // 0 = q, 1 = k
    const int h   = (t >> 5) & 15;
    const int r   = t >> 9;            // 0..4095
    const int l   = r >> 1;            // sequence position

    float ang = (float)l * c_theta[j];
    float sn, cs;
    sincosf(ang, &sn, &cs);

    float* base = g_qkv + r * E3 + h * 192 + sqk * 64;
    float x0 = base[j];
    float x1 = base[j + 16];
    base[j]      = x0 * cs - x1 * sn;
    base[j + 16] = x1 * cs + x0 * sn;
}

// ---------------------------------------------------------------------------
// Kernel 3: flash-style attention.  One CTA = one (h, b, 64-query tile).
// 256 threads as 16x16; each thread owns a 4x4 micro-tile of S / O.
// Online softmax over 32 KV tiles of 64 keys.
// Dynamic smem: Qs[64][68] + Ks[64][68] + Vs[64][64] + Ps[64][64] = 67,584 B.
// ---------------------------------------------------------------------------
#define ATTN_SMEM_FLOATS (2 * 64 * 68 + 2 * 64 * 64)
#define ATTN_SMEM_BYTES  (ATTN_SMEM_FLOATS * 4)

__global__ void __launch_bounds__(256) attn_kernel(float* __restrict__ out) {
    extern __shared__ __align__(16) float smem[];
    float (*Qs)[68] = reinterpret_cast<float (*)[68]>(smem);
    float (*Ks)[68] = reinterpret_cast<float (*)[68]>(smem + 64 * 68);
    float (*Vs)[64] = reinterpret_cast<float (*)[64]>(smem + 2 * 64 * 68);
    float (*Ps)[64] = reinterpret_cast<float (*)[64]>(smem + 2 * 64 * 68 + 64 * 64);

    const int tid = threadIdx.x;
    const int tx  = tid & 15;
    const int ty  = tid >> 4;
    const int ty4 = ty * 4;
    const int q0  = blockIdx.x * 64;
    const int h   = blockIdx.y;
    const int b   = blockIdx.z;

    const int lr  = tid >> 2;          // 0..63
    const int ld0 = (tid & 3) * 16;    // 0,16,32,48

    // Load Q tile transposed, pre-scaled by 1/sqrt(64)
    const float* Qg = g_qkv + ((q0 + lr) * 2 + b) * E3 + h * 192;
#pragma unroll
    for (int q = 0; q < 4; q++) {
        float4 v = *reinterpret_cast<const float4*>(Qg + ld0 + q * 4);
        Qs[ld0 + q * 4 + 0][lr] = v.x * 0.125f;
        Qs[ld0 + q * 4 + 1][lr] = v.y * 0.125f;
        Qs[ld0 + q * 4 + 2][lr] = v.z * 0.125f;
        Qs[ld0 + q * 4 + 3][lr] = v.w * 0.125f;
    }

    float O[4][4] = {};
    float mi[4]   = {-1e30f, -1e30f, -1e30f, -1e30f};
    float li[4]   = {};

    for (int n0 = 0; n0 < L_SEQ; n0 += 64) {
        const float* Kg = g_qkv + ((n0 + lr) * 2 + b) * E3 + h * 192 + 64;
        const float* Vg = Kg + 64;

        __syncthreads();   // protect K/V/P smem from previous iteration
#pragma unroll
        for (int q = 0; q < 4; q++) {
            float4 kv = *reinterpret_cast<const float4*>(Kg + ld0 + q * 4);
            Ks[ld0 + q * 4 + 0][lr] = kv.x;
            Ks[ld0 + q * 4 + 1][lr] = kv.y;
            Ks[ld0 + q * 4 + 2][lr] = kv.z;
            Ks[ld0 + q * 4 + 3][lr] = kv.w;
            *reinterpret_cast<float4*>(&Vs[lr][ld0 + q * 4]) =
                *reinterpret_cast<const float4*>(Vg + ld0 + q * 4);
        }
        __syncthreads();

        // S = (Q * scale) @ K^T   (64x64x64)
        float s[4][4] = {};
#pragma unroll 16
        for (int kk = 0; kk < 64; kk++) {
            float4 qv = *reinterpret_cast<const float4*>(&Qs[kk][ty4]);
            float4 kv = *reinterpret_cast<const float4*>(&Ks[kk][tx * 4]);
            float qa[4] = {qv.x, qv.y, qv.z, qv.w};
            float kb[4] = {kv.x, kv.y, kv.z, kv.w};
#pragma unroll
            for (int i = 0; i < 4; i++)
#pragma unroll
                for (int j = 0; j < 4; j++)
                    s[i][j] += qa[i] * kb[j];
        }

        // Online softmax (row reductions over the 16 tx lanes via shuffle)
#pragma unroll
        for (int i = 0; i < 4; i++) {
            float tm = fmaxf(fmaxf(s[i][0], s[i][1]), fmaxf(s[i][2], s[i][3]));
#pragma unroll
            for (int off = 1; off < 16; off <<= 1)
                tm = fmaxf(tm, __shfl_xor_sync(0xffffffffu, tm, off));
            float mnew = fmaxf(mi[i], tm);
            float f = __expf(mi[i] - mnew);
            mi[i] = mnew;

            float pr[4];
            float rs = 0.f;
#pragma unroll
            for (int j = 0; j < 4; j++) { pr[j] = __expf(s[i][j] - mnew); rs += pr[j]; }
#pragma unroll
            for (int off = 1; off < 16; off <<= 1)
                rs += __shfl_xor_sync(0xffffffffu, rs, off);

            li[i] = li[i] * f + rs;
#pragma unroll
            for (int j = 0; j < 4; j++) O[i][j] *= f;

            *reinterpret_cast<float4*>(&Ps[ty4 + i][tx * 4]) =
                make_float4(pr[0], pr[1], pr[2], pr[3]);
        }
        __syncthreads();

        // O += P @ V   (64x64x64); P rows broadcast-read per ty-group
#pragma unroll 8
        for (int n = 0; n < 64; n++) {
            float4 vv = *reinterpret_cast<const float4*>(&Vs[n][tx * 4]);
            float p0 = Ps[ty4 + 0][n];
            float p1 = Ps[ty4 + 1][n];
            float p2 = Ps[ty4 + 2][n];
            float p3 = Ps[ty4 + 3][n];
            O[0][0] += p0 * vv.x; O[0][1] += p0 * vv.y; O[0][2] += p0 * vv.z; O[0][3] += p0 * vv.w;
            O[1][0] += p1 * vv.x; O[1][1] += p1 * vv.y; O[1][2] += p1 * vv.z; O[1][3] += p1 * vv.w;
            O[2][0] += p2 * vv.x; O[2][1] += p2 * vv.y; O[2][2] += p2 * vv.z; O[2][3] += p2 * vv.w;
            O[3][0] += p3 * vv.x; O[3][1] += p3 * vv.y; O[3][2] += p3 * vv.z; O[3][3] += p3 * vv.w;
        }
    }

    // Epilogue: normalize and scatter to out[l][b][h*64 + d]
#pragma unroll
    for (int i = 0; i < 4; i++) {
        float inv = 1.0f / li[i];
        int l = q0 + ty4 + i;
        float4 o = make_float4(O[i][0] * inv, O[i][1] * inv, O[i][2] * inv, O[i][3] * inv);
        *reinterpret_cast<float4*>(out + (l * 2 + b) * DMODEL + h * 64 + tx * 4) = o;
    }
}

// ---------------------------------------------------------------------------
extern "C" void kernel_launch(void* const* d_in, const int* in_sizes, int n_in,
                              void* d_out, int out_size) {
    const float* x = (const float*)d_in[0];
    const float* w = (const float*)d_in[1];
    // Robustness: identify operands by element count (x: 4,194,304 / W: 3,145,728)
    if (n_in >= 2 && in_sizes[0] == E3 * DMODEL && in_sizes[1] == NROWS * DMODEL) {
        const float* t = x; x = w; w = t;
    }
    float* out = (float*)d_out;

    static bool attr_set = false;
    if (!attr_set) {
        cudaFuncSetAttribute(attn_kernel, cudaFuncAttributeMaxDynamicSharedMemorySize,
                             ATTN_SMEM_BYTES);
        attr_set = true;
    }

    qkv_gemm<<<dim3(E3 / 64, NROWS / 64), 256>>>(x, w);
    rope_kernel<<<(NROWS * NHEADS * 2 * 16) / 256, 256>>>();
    attn_kernel<<<dim3(L_SEQ / 64, NHEADS, BATCH), 256, ATTN_SMEM_BYTES>>>(out);
}

// round 2
// speedup vs baseline: 1.2539x; 1.2539x over previous
#include <cuda_runtime.h>
#include <cuda_bf16.h>

#define L_SEQ  2048
#define BATCH  2
#define DMODEL 1024
#define NHEADS 16
#define DK     64
#define E3     3072           // 3 * DMODEL
#define NROWS  4096           // L_SEQ * BATCH

// Scratch for projected QKV: [NROWS][E3], row r = l*BATCH + b, col e = h*192 + {q:0..63, k:64..127, v:128..191}
__device__ float g_qkv[NROWS * E3];

// bf16 hi/lo splits of X and W (built once per launch by split kernels)
__device__ __align__(16) __nv_bfloat16 g_xhi[NROWS * DMODEL];
__device__ __align__(16) __nv_bfloat16 g_xlo[NROWS * DMODEL];
__device__ __align__(16) __nv_bfloat16 g_whi[E3 * DMODEL];
__device__ __align__(16) __nv_bfloat16 g_wlo[E3 * DMODEL];

// theta_j = 10000^(-j/16) = 10^(-j/4), exact fp32-rounded constants
__constant__ float c_theta[16] = {
    1.0f,                     0.5623413251903491f,     0.31622776601683794f,   0.17782794100389228f,
    0.1f,                     0.05623413251903491f,    0.031622776601683794f,  0.017782794100389228f,
    0.01f,                    0.005623413251903491f,   0.0031622776601683794f, 0.0017782794100389228f,
    0.001f,                   0.0005623413251903491f,  0.00031622776601683794f,0.00017782794100389227f
};

// ---------------------------------------------------------------------------
// Split kernels: fp32 -> bf16 hi + bf16 lo (residual).
// ---------------------------------------------------------------------------
__device__ __forceinline__ void split4(const float4 v, __nv_bfloat16* hi, __nv_bfloat16* lo, int i4) {
    float vs[4] = {v.x, v.y, v.z, v.w};
    unsigned hp[2], lp[2];
#pragma unroll
    for (int p = 0; p < 2; p++) {
        __nv_bfloat16 h0 = __float2bfloat16_rn(vs[2 * p]);
        __nv_bfloat16 h1 = __float2bfloat16_rn(vs[2 * p + 1]);
        __nv_bfloat16 l0 = __float2bfloat16_rn(vs[2 * p] - __bfloat162float(h0));
        __nv_bfloat16 l1 = __float2bfloat16_rn(vs[2 * p + 1] - __bfloat162float(h1));
        __nv_bfloat162 hh; hh.x = h0; hh.y = h1;
        __nv_bfloat162 ll; ll.x = l0; ll.y = l1;
        hp[p] = *reinterpret_cast<unsigned*>(&hh);
        lp[p] = *reinterpret_cast<unsigned*>(&ll);
    }
    reinterpret_cast<uint2*>(hi)[i4] = make_uint2(hp[0], hp[1]);
    reinterpret_cast<uint2*>(lo)[i4] = make_uint2(lp[0], lp[1]);
}

__global__ void __launch_bounds__(256) split_x(const float* __restrict__ src) {
    int t = blockIdx.x * 256 + threadIdx.x;         // one float4 per thread
    split4(reinterpret_cast<const float4*>(src)[t], g_xhi, g_xlo, t);
}
__global__ void __launch_bounds__(256) split_w(const float* __restrict__ src) {
    int t = blockIdx.x * 256 + threadIdx.x;
    split4(reinterpret_cast<const float4*>(src)[t], g_whi, g_wlo, t);
}

// ---------------------------------------------------------------------------
// Kernel 1: QKV projection GEMM on tensor cores (bf16x3 split).
// qkv[r][e] = sum_d X[r][d] * W[e][d]
// CTA tile 128(M) x 64(N), BK=32, 8 warps (4 x 2), warp tile 32x32.
// mma.sync.m16n8k16 bf16, fp32 accumulate; D = Xhi*Whi + Xhi*Wlo + Xlo*Whi.
// ---------------------------------------------------------------------------
#define MMA_BF16(C, A, B)                                                        \
    asm volatile("mma.sync.aligned.m16n8k16.row.col.f32.bf16.bf16.f32 "          \
                 "{%0,%1,%2,%3}, {%4,%5,%6,%7}, {%8,%9}, {%0,%1,%2,%3};"         \
                 : "+f"((C)[0]), "+f"((C)[1]), "+f"((C)[2]), "+f"((C)[3])        \
                 : "r"((A)[0]), "r"((A)[1]), "r"((A)[2]), "r"((A)[3]),           \
                   "r"((B)[0]), "r"((B)[1]))

#define LDSU32(p) (*reinterpret_cast<const unsigned*>(p))

#define BK 32
#define KPAD 40   // bf16 elements per smem row (32 + 8 pad): conflict-free frag loads

__global__ void __launch_bounds__(256) qkv_gemm_tc() {
    __shared__ __align__(16) __nv_bfloat16 sAhi[128][KPAD];
    __shared__ __align__(16) __nv_bfloat16 sAlo[128][KPAD];
    __shared__ __align__(16) __nv_bfloat16 sBhi[64][KPAD];
    __shared__ __align__(16) __nv_bfloat16 sBlo[64][KPAD];

    const int tid   = threadIdx.x;
    const int wid   = tid >> 5;
    const int lane  = tid & 31;
    const int warpM = wid >> 1;            // 0..3 -> m offset *32
    const int warpN = wid & 1;             // 0..1 -> n offset *32
    const int r0    = blockIdx.y * 128;
    const int e0    = blockIdx.x * 64;

    const int fr = lane >> 2;              // 0..7
    const int fc = (lane & 3) * 2;         // 0,2,4,6

    // Load mapping: t -> (row = t/4, 16B chunk = t%4) ; A covers rows t/4 and t/4+64
    const int mA = tid >> 2;
    const int kc = (tid & 3) * 8;          // bf16 offset of chunk

    const __nv_bfloat16* pXh = g_xhi + (size_t)(r0 + mA) * DMODEL + kc;
    const __nv_bfloat16* pXl = g_xlo + (size_t)(r0 + mA) * DMODEL + kc;
    const __nv_bfloat16* pWh = g_whi + (size_t)(e0 + mA) * DMODEL + kc;
    const __nv_bfloat16* pWl = g_wlo + (size_t)(e0 + mA) * DMODEL + kc;

    float acc[2][4][4] = {};

    uint4 pah0, pah1, pal0, pal1, pbh, pbl;
#define LOAD_TILES(K0)                                                               \
    do {                                                                             \
        pah0 = *reinterpret_cast<const uint4*>(pXh + (K0));                          \
        pah1 = *reinterpret_cast<const uint4*>(pXh + (K0) + 64 * DMODEL);            \
        pal0 = *reinterpret_cast<const uint4*>(pXl + (K0));                          \
        pal1 = *reinterpret_cast<const uint4*>(pXl + (K0) + 64 * DMODEL);            \
        pbh  = *reinterpret_cast<const uint4*>(pWh + (K0));                          \
        pbl  = *reinterpret_cast<const uint4*>(pWl + (K0));                          \
    } while (0)

    LOAD_TILES(0);

    for (int kt = 0; kt < DMODEL / BK; kt++) {
        __syncthreads();
        *reinterpret_cast<uint4*>(&sAhi[mA][kc])      = pah0;
        *reinterpret_cast<uint4*>(&sAhi[mA + 64][kc]) = pah1;
        *reinterpret_cast<uint4*>(&sAlo[mA][kc])      = pal0;
        *reinterpret_cast<uint4*>(&sAlo[mA + 64][kc]) = pal1;
        *reinterpret_cast<uint4*>(&sBhi[mA][kc])      = pbh;
        *reinterpret_cast<uint4*>(&sBlo[mA][kc])      = pbl;
        __syncthreads();

        if (kt + 1 < DMODEL / BK) LOAD_TILES((kt + 1) * BK);

#pragma unroll
        for (int ks = 0; ks < BK; ks += 16) {
            unsigned ahi[2][4], alo[2][4], bhi[4][2], blo[4][2];
#pragma unroll
            for (int am = 0; am < 2; am++) {
                const int rb = warpM * 32 + am * 16 + fr;
                ahi[am][0] = LDSU32(&sAhi[rb][ks + fc]);
                ahi[am][1] = LDSU32(&sAhi[rb + 8][ks + fc]);
                ahi[am][2] = LDSU32(&sAhi[rb][ks + fc + 8]);
                ahi[am][3] = LDSU32(&sAhi[rb + 8][ks + fc + 8]);
                alo[am][0] = LDSU32(&sAlo[rb][ks + fc]);
                alo[am][1] = LDSU32(&sAlo[rb + 8][ks + fc]);
                alo[am][2] = LDSU32(&sAlo[rb][ks + fc + 8]);
                alo[am][3] = LDSU32(&sAlo[rb + 8][ks + fc + 8]);
            }
#pragma unroll
            for (int bn = 0; bn < 4; bn++) {
                const int nb = warpN * 32 + bn * 8 + fr;
                bhi[bn][0] = LDSU32(&sBhi[nb][ks + fc]);
                bhi[bn][1] = LDSU32(&sBhi[nb][ks + fc + 8]);
                blo[bn][0] = LDSU32(&sBlo[nb][ks + fc]);
                blo[bn][1] = LDSU32(&sBlo[nb][ks + fc + 8]);
            }
#pragma unroll
            for (int am = 0; am < 2; am++)
#pragma unroll
                for (int bn = 0; bn < 4; bn++) {
                    MMA_BF16(acc[am][bn], ahi[am], bhi[bn]);
                    MMA_BF16(acc[am][bn], ahi[am], blo[bn]);
                    MMA_BF16(acc[am][bn], alo[am], bhi[bn]);
                }
        }
    }

    // Epilogue: C frag (r, 2c), (r, 2c+1), (r+8, 2c), (r+8, 2c+1)
#pragma unroll
    for (int am = 0; am < 2; am++)
#pragma unroll
        for (int bn = 0; bn < 4; bn++) {
            const int row = r0 + warpM * 32 + am * 16 + fr;
            const int col = e0 + warpN * 32 + bn * 8 + fc;
            *reinterpret_cast<float2*>(&g_qkv[(size_t)row * E3 + col]) =
                make_float2(acc[am][bn][0], acc[am][bn][1]);
            *reinterpret_cast<float2*>(&g_qkv[(size_t)(row + 8) * E3 + col]) =
                make_float2(acc[am][bn][2], acc[am][bn][3]);
        }
}

// ---------------------------------------------------------------------------
// Kernel 2: in-place RoPE on the q and k slices of g_qkv.
// ---------------------------------------------------------------------------
__global__ void __launch_bounds__(256) rope_kernel() {
    const int t   = blockIdx.x * 256 + threadIdx.x;
    const int j   = t & 15;
    const int sqk = (t >> 4) & 1;      // 0 = q, 1 = k
    const int h   = (t >> 5) & 15;
    const int r   = t >> 9;            // 0..4095
    const int l   = r >> 1;            // sequence position

    float ang = (float)l * c_theta[j];
    float sn, cs;
    sincosf(ang, &sn, &cs);

    float* base = g_qkv + r * E3 + h * 192 + sqk * 64;
    float x0 = base[j];
    float x1 = base[j + 16];
    base[j]      = x0 * cs - x1 * sn;
    base[j + 16] = x1 * cs + x0 * sn;
}

// ---------------------------------------------------------------------------
// Kernel 3: flash-style attention (unchanged SIMT this round).
// ---------------------------------------------------------------------------
#define ATTN_SMEM_FLOATS (2 * 64 * 68 + 2 * 64 * 64)
#define ATTN_SMEM_BYTES  (ATTN_SMEM_FLOATS * 4)

__global__ void __launch_bounds__(256) attn_kernel(float* __restrict__ out) {
    extern __shared__ __align__(16) float smem[];
    float (*Qs)[68] = reinterpret_cast<float (*)[68]>(smem);
    float (*Ks)[68] = reinterpret_cast<float (*)[68]>(smem + 64 * 68);
    float (*Vs)[64] = reinterpret_cast<float (*)[64]>(smem + 2 * 64 * 68);
    float (*Ps)[64] = reinterpret_cast<float (*)[64]>(smem + 2 * 64 * 68 + 64 * 64);

    const int tid = threadIdx.x;
    const int tx  = tid & 15;
    const int ty  = tid >> 4;
    const int ty4 = ty * 4;
    const int q0  = blockIdx.x * 64;
    const int h   = blockIdx.y;
    const int b   = blockIdx.z;

    const int lr  = tid >> 2;          // 0..63
    const int ld0 = (tid & 3) * 16;    // 0,16,32,48

    const float* Qg = g_qkv + ((q0 + lr) * 2 + b) * E3 + h * 192;
#pragma unroll
    for (int q = 0; q < 4; q++) {
        float4 v = *reinterpret_cast<const float4*>(Qg + ld0 + q * 4);
        Qs[ld0 + q * 4 + 0][lr] = v.x * 0.125f;
        Qs[ld0 + q * 4 + 1][lr] = v.y * 0.125f;
        Qs[ld0 + q * 4 + 2][lr] = v.z * 0.125f;
        Qs[ld0 + q * 4 + 3][lr] = v.w * 0.125f;
    }

    float O[4][4] = {};
    float mi[4]   = {-1e30f, -1e30f, -1e30f, -1e30f};
    float li[4]   = {};

    for (int n0 = 0; n0 < L_SEQ; n0 += 64) {
        const float* Kg = g_qkv + ((n0 + lr) * 2 + b) * E3 + h * 192 + 64;
        const float* Vg = Kg + 64;

        __syncthreads();
#pragma unroll
        for (int q = 0; q < 4; q++) {
            float4 kv = *reinterpret_cast<const float4*>(Kg + ld0 + q * 4);
            Ks[ld0 + q * 4 + 0][lr] = kv.x;
            Ks[ld0 + q * 4 + 1][lr] = kv.y;
            Ks[ld0 + q * 4 + 2][lr] = kv.z;
            Ks[ld0 + q * 4 + 3][lr] = kv.w;
            *reinterpret_cast<float4*>(&Vs[lr][ld0 + q * 4]) =
                *reinterpret_cast<const float4*>(Vg + ld0 + q * 4);
        }
        __syncthreads();

        float s[4][4] = {};
#pragma unroll 16
        for (int kk = 0; kk < 64; kk++) {
            float4 qv = *reinterpret_cast<const float4*>(&Qs[kk][ty4]);
            float4 kv = *reinterpret_cast<const float4*>(&Ks[kk][tx * 4]);
            float qa[4] = {qv.x, qv.y, qv.z, qv.w};
            float kb[4] = {kv.x, kv.y, kv.z, kv.w};
#pragma unroll
            for (int i = 0; i < 4; i++)
#pragma unroll
                for (int j = 0; j < 4; j++)
                    s[i][j] += qa[i] * kb[j];
        }

#pragma unroll
        for (int i = 0; i < 4; i++) {
            float tm = fmaxf(fmaxf(s[i][0], s[i][1]), fmaxf(s[i][2], s[i][3]));
#pragma unroll
            for (int off = 1; off < 16; off <<= 1)
                tm = fmaxf(tm, __shfl_xor_sync(0xffffffffu, tm, off));
            float mnew = fmaxf(mi[i], tm);
            float f = __expf(mi[i] - mnew);
            mi[i] = mnew;

            float pr[4];
            float rs = 0.f;
#pragma unroll
            for (int j = 0; j < 4; j++) { pr[j] = __expf(s[i][j] - mnew); rs += pr[j]; }
#pragma unroll
            for (int off = 1; off < 16; off <<= 1)
                rs += __shfl_xor_sync(0xffffffffu, rs, off);

            li[i] = li[i] * f + rs;
#pragma unroll
            for (int j = 0; j < 4; j++) O[i][j] *= f;

            *reinterpret_cast<float4*>(&Ps[ty4 + i][tx * 4]) =
                make_float4(pr[0], pr[1], pr[2], pr[3]);
        }
        __syncthreads();

#pragma unroll 8
        for (int n = 0; n < 64; n++) {
            float4 vv = *reinterpret_cast<const float4*>(&Vs[n][tx * 4]);
            float p0 = Ps[ty4 + 0][n];
            float p1 = Ps[ty4 + 1][n];
            float p2 = Ps[ty4 + 2][n];
            float p3 = Ps[ty4 + 3][n];
            O[0][0] += p0 * vv.x; O[0][1] += p0 * vv.y; O[0][2] += p0 * vv.z; O[0][3] += p0 * vv.w;
            O[1][0] += p1 * vv.x; O[1][1] += p1 * vv.y; O[1][2] += p1 * vv.z; O[1][3] += p1 * vv.w;
            O[2][0] += p2 * vv.x; O[2][1] += p2 * vv.y; O[2][2] += p2 * vv.z; O[2][3] += p2 * vv.w;
            O[3][0] += p3 * vv.x; O[3][1] += p3 * vv.y; O[3][2] += p3 * vv.z; O[3][3] += p3 * vv.w;
        }
    }

#pragma unroll
    for (int i = 0; i < 4; i++) {
        float inv = 1.0f / li[i];
        int l = q0 + ty4 + i;
        float4 o = make_float4(O[i][0] * inv, O[i][1] * inv, O[i][2] * inv, O[i][3] * inv);
        *reinterpret_cast<float4*>(out + (l * 2 + b) * DMODEL + h * 64 + tx * 4) = o;
    }
}

// ---------------------------------------------------------------------------
extern "C" void kernel_launch(void* const* d_in, const int* in_sizes, int n_in,
                              void* d_out, int out_size) {
    const float* x = (const float*)d_in[0];
    const float* w = (const float*)d_in[1];
    if (n_in >= 2 && in_sizes[0] == E3 * DMODEL && in_sizes[1] == NROWS * DMODEL) {
        const float* t = x; x = w; w = t;
    }
    float* out = (float*)d_out;

    static bool attr_set = false;
    if (!attr_set) {
        cudaFuncSetAttribute(attn_kernel, cudaFuncAttributeMaxDynamicSharedMemorySize,
                             ATTN_SMEM_BYTES);
        attr_set = true;
    }

    split_x<<<(NROWS * DMODEL / 4) / 256, 256>>>(x);
    split_w<<<(E3 * DMODEL / 4) / 256, 256>>>(w);
    qkv_gemm_tc<<<dim3(E3 / 64, NROWS / 128), 256>>>();
    rope_kernel<<<(NROWS * NHEADS * 2 * 16) / 256, 256>>>();
    attn_kernel<<<dim3(L_SEQ / 64, NHEADS, BATCH), 256, ATTN_SMEM_BYTES>>>(out);
}

// round 4
// speedup vs baseline: 2.6722x; 2.1311x over previous
#include <cuda_runtime.h>
#include <cuda_bf16.h>

#define L_SEQ  2048
#define BATCH  2
#define DMODEL 1024
#define NHEADS 16
#define DK     64
#define E3     3072
#define NROWS  4096

// fp32 QKV projection scratch: [NROWS][E3], row r = l*BATCH + b, col e = h*192 + {q,k,v}
__device__ float g_qkv[NROWS * E3];

// bf16 hi/lo splits of X and W for the projection GEMM
__device__ __align__(16) __nv_bfloat16 g_xhi[NROWS * DMODEL];
__device__ __align__(16) __nv_bfloat16 g_xlo[NROWS * DMODEL];
__device__ __align__(16) __nv_bfloat16 g_whi[E3 * DMODEL];
__device__ __align__(16) __nv_bfloat16 g_wlo[E3 * DMODEL];

// Attention operand buffers (bf16 hi/lo).
// Q,K: [b][h][l][d] (rope applied; Q pre-scaled by 0.125*log2e). V: [b][h][d][l] (transposed).
#define QKV_ELEMS (BATCH * NHEADS * L_SEQ * DK)
__device__ __align__(16) __nv_bfloat16 g_qhi[QKV_ELEMS];
__device__ __align__(16) __nv_bfloat16 g_qlo[QKV_ELEMS];
__device__ __align__(16) __nv_bfloat16 g_khi[QKV_ELEMS];
__device__ __align__(16) __nv_bfloat16 g_klo[QKV_ELEMS];
__device__ __align__(16) __nv_bfloat16 g_vhi[QKV_ELEMS];
__device__ __align__(16) __nv_bfloat16 g_vlo[QKV_ELEMS];

__constant__ float c_theta[16] = {
    1.0f,                     0.5623413251903491f,     0.31622776601683794f,   0.17782794100389228f,
    0.1f,                     0.05623413251903491f,    0.031622776601683794f,  0.017782794100389228f,
    0.01f,                    0.005623413251903491f,   0.0031622776601683794f, 0.0017782794100389228f,
    0.001f,                   0.0005623413251903491f,  0.00031622776601683794f,0.00017782794100389227f
};

// ---------------------------------------------------------------------------
// Helpers
// ---------------------------------------------------------------------------
#define MMA_BF16(C, A, B)                                                        \
    asm volatile("mma.sync.aligned.m16n8k16.row.col.f32.bf16.bf16.f32 "          \
                 "{%0,%1,%2,%3}, {%4,%5,%6,%7}, {%8,%9}, {%0,%1,%2,%3};"         \
                 : "+f"((C)[0]), "+f"((C)[1]), "+f"((C)[2]), "+f"((C)[3])        \
                 : "r"((A)[0]), "r"((A)[1]), "r"((A)[2]), "r"((A)[3]),           \
                   "r"((B)[0]), "r"((B)[1]))

#define LDSU32(p) (*reinterpret_cast<const unsigned*>(p))

__device__ __forceinline__ float ex2f(float x) {
    float r;
    asm("ex2.approx.ftz.f32 %0, %1;" : "=f"(r) : "f"(x));
    return r;
}

__device__ __forceinline__ void cp16(unsigned s, const void* g) {
    asm volatile("cp.async.ca.shared.global [%0], [%1], 16;" :: "r"(s), "l"(g));
}

__device__ __forceinline__ void pack_hilo(float f0, float f1, unsigned& h, unsigned& l) {
    __nv_bfloat162 hb = __floats2bfloat162_rn(f0, f1);
    float r0 = f0 - __bfloat162float(hb.x);
    float r1 = f1 - __bfloat162float(hb.y);
    __nv_bfloat162 lb = __floats2bfloat162_rn(r0, r1);
    h = *reinterpret_cast<unsigned*>(&hb);
    l = *reinterpret_cast<unsigned*>(&lb);
}

// ---------------------------------------------------------------------------
// Split kernels: fp32 -> bf16 hi + bf16 lo
// ---------------------------------------------------------------------------
__device__ __forceinline__ void split4(const float4 v, __nv_bfloat16* hi, __nv_bfloat16* lo, int i4) {
    float vs[4] = {v.x, v.y, v.z, v.w};
    unsigned hp[2], lp[2];
#pragma unroll
    for (int p = 0; p < 2; p++) pack_hilo(vs[2 * p], vs[2 * p + 1], hp[p], lp[p]);
    reinterpret_cast<uint2*>(hi)[i4] = make_uint2(hp[0], hp[1]);
    reinterpret_cast<uint2*>(lo)[i4] = make_uint2(lp[0], lp[1]);
}

__global__ void __launch_bounds__(256) split_x(const float* __restrict__ src) {
    int t = blockIdx.x * 256 + threadIdx.x;
    split4(reinterpret_cast<const float4*>(src)[t], g_xhi, g_xlo, t);
}
__global__ void __launch_bounds__(256) split_w(const float* __restrict__ src) {
    int t = blockIdx.x * 256 + threadIdx.x;
    split4(reinterpret_cast<const float4*>(src)[t], g_whi, g_wlo, t);
}

// ---------------------------------------------------------------------------
// Kernel 1: QKV projection GEMM (bf16x3 mma.sync) — unchanged from round 2
// ---------------------------------------------------------------------------
#define BK 32
#define KPAD 40

__global__ void __launch_bounds__(256) qkv_gemm_tc() {
    __shared__ __align__(16) __nv_bfloat16 sAhi[128][KPAD];
    __shared__ __align__(16) __nv_bfloat16 sAlo[128][KPAD];
    __shared__ __align__(16) __nv_bfloat16 sBhi[64][KPAD];
    __shared__ __align__(16) __nv_bfloat16 sBlo[64][KPAD];

    const int tid   = threadIdx.x;
    const int wid   = tid >> 5;
    const int lane  = tid & 31;
    const int warpM = wid >> 1;
    const int warpN = wid & 1;
    const int r0    = blockIdx.y * 128;
    const int e0    = blockIdx.x * 64;

    const int fr = lane >> 2;
    const int fc = (lane & 3) * 2;

    const int mA = tid >> 2;
    const int kc = (tid & 3) * 8;

    const __nv_bfloat16* pXh = g_xhi + (size_t)(r0 + mA) * DMODEL + kc;
    const __nv_bfloat16* pXl = g_xlo + (size_t)(r0 + mA) * DMODEL + kc;
    const __nv_bfloat16* pWh = g_whi + (size_t)(e0 + mA) * DMODEL + kc;
    const __nv_bfloat16* pWl = g_wlo + (size_t)(e0 + mA) * DMODEL + kc;

    float acc[2][4][4] = {};

    uint4 pah0, pah1, pal0, pal1, pbh, pbl;
#define LOAD_TILES(K0)                                                               \
    do {                                                                             \
        pah0 = *reinterpret_cast<const uint4*>(pXh + (K0));                          \
        pah1 = *reinterpret_cast<const uint4*>(pXh + (K0) + 64 * DMODEL);            \
        pal0 = *reinterpret_cast<const uint4*>(pXl + (K0));                          \
        pal1 = *reinterpret_cast<const uint4*>(pXl + (K0) + 64 * DMODEL);            \
        pbh  = *reinterpret_cast<const uint4*>(pWh + (K0));                          \
        pbl  = *reinterpret_cast<const uint4*>(pWl + (K0));                          \
    } while (0)

    LOAD_TILES(0);

    for (int kt = 0; kt < DMODEL / BK; kt++) {
        __syncthreads();
        *reinterpret_cast<uint4*>(&sAhi[mA][kc])      = pah0;
        *reinterpret_cast<uint4*>(&sAhi[mA + 64][kc]) = pah1;
        *reinterpret_cast<uint4*>(&sAlo[mA][kc])      = pal0;
        *reinterpret_cast<uint4*>(&sAlo[mA + 64][kc]) = pal1;
        *reinterpret_cast<uint4*>(&sBhi[mA][kc])      = pbh;
        *reinterpret_cast<uint4*>(&sBlo[mA][kc])      = pbl;
        __syncthreads();

        if (kt + 1 < DMODEL / BK) LOAD_TILES((kt + 1) * BK);

#pragma unroll
        for (int ks = 0; ks < BK; ks += 16) {
            unsigned ahi[2][4], alo[2][4], bhi[4][2], blo[4][2];
#pragma unroll
            for (int am = 0; am < 2; am++) {
                const int rb = warpM * 32 + am * 16 + fr;
                ahi[am][0] = LDSU32(&sAhi[rb][ks + fc]);
                ahi[am][1] = LDSU32(&sAhi[rb + 8][ks + fc]);
                ahi[am][2] = LDSU32(&sAhi[rb][ks + fc + 8]);
                ahi[am][3] = LDSU32(&sAhi[rb + 8][ks + fc + 8]);
                alo[am][0] = LDSU32(&sAlo[rb][ks + fc]);
                alo[am][1] = LDSU32(&sAlo[rb + 8][ks + fc]);
                alo[am][2] = LDSU32(&sAlo[rb][ks + fc + 8]);
                alo[am][3] = LDSU32(&sAlo[rb + 8][ks + fc + 8]);
            }
#pragma unroll
            for (int bn = 0; bn < 4; bn++) {
                const int nb = warpN * 32 + bn * 8 + fr;
                bhi[bn][0] = LDSU32(&sBhi[nb][ks + fc]);
                bhi[bn][1] = LDSU32(&sBhi[nb][ks + fc + 8]);
                blo[bn][0] = LDSU32(&sBlo[nb][ks + fc]);
                blo[bn][1] = LDSU32(&sBlo[nb][ks + fc + 8]);
            }
#pragma unroll
            for (int am = 0; am < 2; am++)
#pragma unroll
                for (int bn = 0; bn < 4; bn++) {
                    MMA_BF16(acc[am][bn], ahi[am], bhi[bn]);
                    MMA_BF16(acc[am][bn], ahi[am], blo[bn]);
                    MMA_BF16(acc[am][bn], alo[am], bhi[bn]);
                }
        }
    }

#pragma unroll
    for (int am = 0; am < 2; am++)
#pragma unroll
        for (int bn = 0; bn < 4; bn++) {
            const int row = r0 + warpM * 32 + am * 16 + fr;
            const int col = e0 + warpN * 32 + bn * 8 + fc;
            *reinterpret_cast<float2*>(&g_qkv[(size_t)row * E3 + col]) =
                make_float2(acc[am][bn][0], acc[am][bn][1]);
            *reinterpret_cast<float2*>(&g_qkv[(size_t)(row + 8) * E3 + col]) =
                make_float2(acc[am][bn][2], acc[am][bn][3]);
        }
}

// ---------------------------------------------------------------------------
// Kernel 2: rope + split for Q and K -> bf16 hi/lo, layout [b][h][l][d].
// Q additionally scaled by 0.125 * log2(e) (softmax then uses exp2).
// ---------------------------------------------------------------------------
#define QSCALE 0.1803368801111243f   // 0.125 * log2(e)

__global__ void __launch_bounds__(256) prep_qk() {
    const int t   = blockIdx.x * 256 + threadIdx.x;
    const int j   = t & 15;
    const int sqk = (t >> 4) & 1;    // 0 = q, 1 = k
    const int h   = (t >> 5) & 15;
    const int r   = t >> 9;          // 0..4095
    const int l   = r >> 1;
    const int b   = r & 1;

    const float* base = g_qkv + (size_t)r * E3 + h * 192 + sqk * 64;
    float x0 = base[j];
    float x1 = base[j + 16];
    float p0 = base[j + 32];
    float p1 = base[j + 48];

    float ang = (float)l * c_theta[j];
    float sn, cs;
    sincosf(ang, &sn, &cs);
    float y0 = x0 * cs - x1 * sn;
    float y1 = x1 * cs + x0 * sn;

    const float sc = sqk ? 1.0f : QSCALE;
    y0 *= sc; y1 *= sc; p0 *= sc; p1 *= sc;

    const size_t dst = ((size_t)(b * NHEADS + h) * L_SEQ + l) * DK;
    __nv_bfloat16* dh = (sqk ? g_khi : g_qhi) + dst;
    __nv_bfloat16* dl = (sqk ? g_klo : g_qlo) + dst;

    float vals[4] = {y0, y1, p0, p1};
    int   ds[4]   = {j, j + 16, j + 32, j + 48};
#pragma unroll
    for (int i = 0; i < 4; i++) {
        __nv_bfloat16 hi = __float2bfloat16_rn(vals[i]);
        dh[ds[i]] = hi;
        dl[ds[i]] = __float2bfloat16_rn(vals[i] - __bfloat162float(hi));
    }
}

// ---------------------------------------------------------------------------
// Kernel 3: V transpose + split -> bf16 hi/lo, layout [b][h][d][l].
// One CTA per (kv-tile 64, h, b); 128 threads.
// ---------------------------------------------------------------------------
__global__ void __launch_bounds__(128) prep_v() {
    __shared__ float s[64][68];
    const int tile = blockIdx.x, h = blockIdx.y, b = blockIdx.z;
    const int tid = threadIdx.x;

#pragma unroll
    for (int i = 0; i < 8; i++) {
        int id  = i * 128 + tid;       // 0..1023
        int row = id >> 4;             // kv 0..63
        int c4  = id & 15;
        const float* g = g_qkv + (size_t)((tile * 64 + row) * 2 + b) * E3 + h * 192 + 128 + c4 * 4;
        float4 v = *reinterpret_cast<const float4*>(g);
        s[row][c4 * 4 + 0] = v.x; s[row][c4 * 4 + 1] = v.y;
        s[row][c4 * 4 + 2] = v.z; s[row][c4 * 4 + 3] = v.w;
    }
    __syncthreads();

    const int d = tid & 63, part = tid >> 6;
    const size_t ob = ((size_t)(b * NHEADS + h) * DK + d) * L_SEQ + tile * 64 + part * 32;

#pragma unroll
    for (int kc = 0; kc < 4; kc++) {
        unsigned hw[4], lw[4];
#pragma unroll
        for (int p = 0; p < 4; p++) {
            float v0 = s[part * 32 + kc * 8 + p * 2 + 0][d];
            float v1 = s[part * 32 + kc * 8 + p * 2 + 1][d];
            pack_hilo(v0, v1, hw[p], lw[p]);
        }
        *reinterpret_cast<uint4*>(g_vhi + ob + kc * 8) = make_uint4(hw[0], hw[1], hw[2], hw[3]);
        *reinterpret_cast<uint4*>(g_vlo + ob + kc * 8) = make_uint4(lw[0], lw[1], lw[2], lw[3]);
    }
}

// ---------------------------------------------------------------------------
// Kernel 4: tensor-core flash attention (bf16x3).
// CTA = 128 queries x (h,b). 4 warps, 32 rows each (2 m-frags).
// KV tiles of 64, double-buffered via cp.async. P kept in registers (C->A reuse).
// smem layout (bf16 elems, rows padded to 72):
//   [0]      Qhi 128x72          [9216]   Qlo 128x72
//   [18432 + s*18432] buffer s: Khi 64x72, Klo, Vhi, Vlo (4608 each)
// ---------------------------------------------------------------------------
#define ATTN_SMEM_BYTES ((18432 + 2 * 18432) * 2)

__global__ void __launch_bounds__(128) attn_tc(float* __restrict__ out) {
    extern __shared__ __align__(16) __nv_bfloat16 sm[];
    const unsigned smem_base = (unsigned)__cvta_generic_to_shared(sm);

    const int tid  = threadIdx.x;
    const int w    = tid >> 5;
    const int lane = tid & 31;
    const int g    = lane >> 2;
    const int tg   = lane & 3;

    const int q0 = blockIdx.x * 128;
    const int h  = blockIdx.y;
    const int b  = blockIdx.z;
    const int hb = b * NHEADS + h;

    const size_t qkbase = (size_t)hb * L_SEQ * DK;
    const size_t vbase  = (size_t)hb * DK * L_SEQ;

    // ---- issue Q tile loads (group with tile 0) ----
#pragma unroll
    for (int i = 0; i < 16; i++) {
        int id  = i * 128 + tid;
        int rid = (id >> 3) & 127;
        int ch  = id & 7;
        const __nv_bfloat16* gp = (i < 8 ? g_qhi : g_qlo) + qkbase + (size_t)(q0 + rid) * DK + ch * 8;
        unsigned sp = smem_base + ((i < 8 ? 0 : 9216) + rid * 72 + ch * 8) * 2;
        cp16(sp, gp);
    }

    // ---- tile issue helper (macro for compile-time unrolling) ----
#define ISSUE_TILE(T, BUF)                                                            \
    do {                                                                              \
        _Pragma("unroll")                                                             \
        for (int i = 0; i < 16; i++) {                                                \
            int id  = i * 128 + tid;                                                  \
            int arr = i >> 2;                                                         \
            int rid = (id >> 3) & 63;                                                 \
            int ch  = id & 7;                                                         \
            const __nv_bfloat16* gp;                                                  \
            if (arr == 0)      gp = g_khi + qkbase + (size_t)((T) * 64 + rid) * DK + ch * 8; \
            else if (arr == 1) gp = g_klo + qkbase + (size_t)((T) * 64 + rid) * DK + ch * 8; \
            else if (arr == 2) gp = g_vhi + vbase + (size_t)rid * L_SEQ + (T) * 64 + ch * 8; \
            else               gp = g_vlo + vbase + (size_t)rid * L_SEQ + (T) * 64 + ch * 8; \
            unsigned sp = smem_base + (18432 + (BUF) * 18432 + arr * 4608 + rid * 72 + ch * 8) * 2; \
            cp16(sp, gp);                                                             \
        }                                                                             \
    } while (0)

    ISSUE_TILE(0, 0);
    asm volatile("cp.async.commit_group;");

    float o[2][8][4] = {};
    float mrow[2][2] = {{-1e30f, -1e30f}, {-1e30f, -1e30f}};
    float lrow[2][2] = {};

    const int rb0 = w * 32;   // warp's row base within q-tile

    for (int t = 0; t < 32; t++) {
        const int cur = t & 1;
        if (t < 31) {
            ISSUE_TILE(t + 1, cur ^ 1);
            asm volatile("cp.async.commit_group;");
            asm volatile("cp.async.wait_group 1;");
        } else {
            asm volatile("cp.async.wait_group 0;");
        }
        __syncthreads();

        const __nv_bfloat16* sQh = sm;
        const __nv_bfloat16* sQl = sm + 9216;
        const __nv_bfloat16* sKh = sm + 18432 + cur * 18432;
        const __nv_bfloat16* sKl = sKh + 4608;
        const __nv_bfloat16* sVh = sKh + 9216;
        const __nv_bfloat16* sVl = sKh + 13824;

        // ---- S = Q K^T (bf16x3) ----
        float s[2][8][4] = {};
#pragma unroll
        for (int kf = 0; kf < 4; kf++) {
            unsigned ah[2][4], al[2][4];
#pragma unroll
            for (int mf = 0; mf < 2; mf++) {
                const int r = rb0 + mf * 16 + g;
                ah[mf][0] = LDSU32(&sQh[r * 72 + kf * 16 + tg * 2]);
                ah[mf][1] = LDSU32(&sQh[(r + 8) * 72 + kf * 16 + tg * 2]);
                ah[mf][2] = LDSU32(&sQh[r * 72 + kf * 16 + 8 + tg * 2]);
                ah[mf][3] = LDSU32(&sQh[(r + 8) * 72 + kf * 16 + 8 + tg * 2]);
                al[mf][0] = LDSU32(&sQl[r * 72 + kf * 16 + tg * 2]);
                al[mf][1] = LDSU32(&sQl[(r + 8) * 72 + kf * 16 + tg * 2]);
                al[mf][2] = LDSU32(&sQl[r * 72 + kf * 16 + 8 + tg * 2]);
                al[mf][3] = LDSU32(&sQl[(r + 8) * 72 + kf * 16 + 8 + tg * 2]);
            }
#pragma unroll
            for (int nf = 0; nf < 8; nf++) {
                unsigned bh[2], bl[2];
                const int kr = (nf * 8 + g) * 72 + kf * 16 + tg * 2;
                bh[0] = LDSU32(&sKh[kr]);
                bh[1] = LDSU32(&sKh[kr + 8]);
                bl[0] = LDSU32(&sKl[kr]);
                bl[1] = LDSU32(&sKl[kr + 8]);
#pragma unroll
                for (int mf = 0; mf < 2; mf++) {
                    MMA_BF16(s[mf][nf], ah[mf], bh);
                    MMA_BF16(s[mf][nf], ah[mf], bl);
                    MMA_BF16(s[mf][nf], al[mf], bh);
                }
            }
        }

        // ---- online softmax (scores are already in log2 domain) ----
        unsigned ph[2][4][4], pl[2][4][4];
#pragma unroll
        for (int mf = 0; mf < 2; mf++) {
            float mx0 = -1e30f, mx1 = -1e30f;
#pragma unroll
            for (int nf = 0; nf < 8; nf++) {
                mx0 = fmaxf(mx0, fmaxf(s[mf][nf][0], s[mf][nf][1]));
                mx1 = fmaxf(mx1, fmaxf(s[mf][nf][2], s[mf][nf][3]));
            }
            mx0 = fmaxf(mx0, __shfl_xor_sync(0xffffffffu, mx0, 1));
            mx0 = fmaxf(mx0, __shfl_xor_sync(0xffffffffu, mx0, 2));
            mx1 = fmaxf(mx1, __shfl_xor_sync(0xffffffffu, mx1, 1));
            mx1 = fmaxf(mx1, __shfl_xor_sync(0xffffffffu, mx1, 2));

            float mn0 = fmaxf(mrow[mf][0], mx0);
            float mn1 = fmaxf(mrow[mf][1], mx1);
            float sc0 = ex2f(mrow[mf][0] - mn0);
            float sc1 = ex2f(mrow[mf][1] - mn1);
            mrow[mf][0] = mn0;
            mrow[mf][1] = mn1;

            float rs0 = 0.f, rs1 = 0.f;
#pragma unroll
            for (int nf = 0; nf < 8; nf++) {
                s[mf][nf][0] = ex2f(s[mf][nf][0] - mn0);
                s[mf][nf][1] = ex2f(s[mf][nf][1] - mn0);
                s[mf][nf][2] = ex2f(s[mf][nf][2] - mn1);
                s[mf][nf][3] = ex2f(s[mf][nf][3] - mn1);
                rs0 += s[mf][nf][0] + s[mf][nf][1];
                rs1 += s[mf][nf][2] + s[mf][nf][3];
            }
            rs0 += __shfl_xor_sync(0xffffffffu, rs0, 1);
            rs0 += __shfl_xor_sync(0xffffffffu, rs0, 2);
            rs1 += __shfl_xor_sync(0xffffffffu, rs1, 1);
            rs1 += __shfl_xor_sync(0xffffffffu, rs1, 2);
            lrow[mf][0] = lrow[mf][0] * sc0 + rs0;
            lrow[mf][1] = lrow[mf][1] * sc1 + rs1;

#pragma unroll
            for (int nf = 0; nf < 8; nf++) {
                o[mf][nf][0] *= sc0; o[mf][nf][1] *= sc0;
                o[mf][nf][2] *= sc1; o[mf][nf][3] *= sc1;
            }

            // pack P into A-fragments (hi + residual lo)
#pragma unroll
            for (int kf = 0; kf < 4; kf++) {
                const int n0 = 2 * kf, n1 = 2 * kf + 1;
                pack_hilo(s[mf][n0][0], s[mf][n0][1], ph[mf][kf][0], pl[mf][kf][0]);
                pack_hilo(s[mf][n0][2], s[mf][n0][3], ph[mf][kf][1], pl[mf][kf][1]);
                pack_hilo(s[mf][n1][0], s[mf][n1][1], ph[mf][kf][2], pl[mf][kf][2]);
                pack_hilo(s[mf][n1][2], s[mf][n1][3], ph[mf][kf][3], pl[mf][kf][3]);
            }
        }

        // ---- O += P V (bf16x3) ----
#pragma unroll
        for (int kf = 0; kf < 4; kf++) {
#pragma unroll
            for (int nf = 0; nf < 8; nf++) {
                unsigned bh[2], bl[2];
                const int vr = (nf * 8 + g) * 72 + kf * 16 + tg * 2;
                bh[0] = LDSU32(&sVh[vr]);
                bh[1] = LDSU32(&sVh[vr + 8]);
                bl[0] = LDSU32(&sVl[vr]);
                bl[1] = LDSU32(&sVl[vr + 8]);
#pragma unroll
                for (int mf = 0; mf < 2; mf++) {
                    MMA_BF16(o[mf][nf], ph[mf][kf], bh);
                    MMA_BF16(o[mf][nf], pl[mf][kf], bh);
                    MMA_BF16(o[mf][nf], ph[mf][kf], bl);
                }
            }
        }
        __syncthreads();
    }

    // ---- epilogue: out[l][b][h*64 + d] ----
#pragma unroll
    for (int mf = 0; mf < 2; mf++) {
        const float inv0 = 1.0f / lrow[mf][0];
        const float inv1 = 1.0f / lrow[mf][1];
        const int r0 = q0 + rb0 + mf * 16 + g;
#pragma unroll
        for (int nf = 0; nf < 8; nf++) {
            const int col = h * 64 + nf * 8 + tg * 2;
            *reinterpret_cast<float2*>(out + (size_t)(r0 * 2 + b) * DMODEL + col) =
                make_float2(o[mf][nf][0] * inv0, o[mf][nf][1] * inv0);
            *reinterpret_cast<float2*>(out + (size_t)((r0 + 8) * 2 + b) * DMODEL + col) =
                make_float2(o[mf][nf][2] * inv1, o[mf][nf][3] * inv1);
        }
    }
}

// ---------------------------------------------------------------------------
extern "C" void kernel_launch(void* const* d_in, const int* in_sizes, int n_in,
                              void* d_out, int out_size) {
    const float* x = (const float*)d_in[0];
    const float* w = (const float*)d_in[1];
    if (n_in >= 2 && in_sizes[0] == E3 * DMODEL && in_sizes[1] == NROWS * DMODEL) {
        const float* t = x; x = w; w = t;
    }
    float* out = (float*)d_out;

    static bool attr_set = false;
    if (!attr_set) {
        cudaFuncSetAttribute(attn_tc, cudaFuncAttributeMaxDynamicSharedMemorySize,
                             ATTN_SMEM_BYTES);
        attr_set = true;
    }

    split_x<<<(NROWS * DMODEL / 4) / 256, 256>>>(x);
    split_w<<<(E3 * DMODEL / 4) / 256, 256>>>(w);
    qkv_gemm_tc<<<dim3(E3 / 64, NROWS / 128), 256>>>();
    prep_qk<<<(NROWS * NHEADS * 2 * 16) / 256, 256>>>();
    prep_v<<<dim3(L_SEQ / 64, NHEADS, BATCH), 128>>>();
    attn_tc<<<dim3(L_SEQ / 128, NHEADS, BATCH), 128, ATTN_SMEM_BYTES>>>(out);
}

// round 6
// speedup vs baseline: 3.0230x; 1.1313x over previous
#include <cuda_runtime.h>
#include <cuda_bf16.h>

#define L_SEQ  2048
#define BATCH  2
#define DMODEL 1024
#define NHEADS 16
#define DK     64
#define E3     3072
#define NROWS  4096

// fp32 QKV projection scratch: [NROWS][E3], row r = l*BATCH + b, col e = h*192 + {q,k,v}
__device__ float g_qkv[NROWS * E3];

// bf16 hi/lo splits of X and W for the projection GEMM
__device__ __align__(16) __nv_bfloat16 g_xhi[NROWS * DMODEL];
__device__ __align__(16) __nv_bfloat16 g_xlo[NROWS * DMODEL];
__device__ __align__(16) __nv_bfloat16 g_whi[E3 * DMODEL];
__device__ __align__(16) __nv_bfloat16 g_wlo[E3 * DMODEL];

// Attention operand buffers (bf16 hi/lo).
// Q,K: [b][h][l][d] (rope applied; Q pre-scaled by 0.125*log2e). V: [b][h][d][l].
#define QKV_ELEMS (BATCH * NHEADS * L_SEQ * DK)
__device__ __align__(16) __nv_bfloat16 g_qhi[QKV_ELEMS];
__device__ __align__(16) __nv_bfloat16 g_qlo[QKV_ELEMS];
__device__ __align__(16) __nv_bfloat16 g_khi[QKV_ELEMS];
__device__ __align__(16) __nv_bfloat16 g_klo[QKV_ELEMS];
__device__ __align__(16) __nv_bfloat16 g_vhi[QKV_ELEMS];
__device__ __align__(16) __nv_bfloat16 g_vlo[QKV_ELEMS];

__constant__ float c_theta[16] = {
    1.0f,                     0.5623413251903491f,     0.31622776601683794f,   0.17782794100389228f,
    0.1f,                     0.05623413251903491f,    0.031622776601683794f,  0.017782794100389228f,
    0.01f,                    0.005623413251903491f,   0.0031622776601683794f, 0.0017782794100389228f,
    0.001f,                   0.0005623413251903491f,  0.00031622776601683794f,0.00017782794100389227f
};

// ---------------------------------------------------------------------------
// Helpers
// ---------------------------------------------------------------------------
#define MMA_BF16(C, A, B)                                                        \
    asm volatile("mma.sync.aligned.m16n8k16.row.col.f32.bf16.bf16.f32 "          \
                 "{%0,%1,%2,%3}, {%4,%5,%6,%7}, {%8,%9}, {%0,%1,%2,%3};"         \
                 : "+f"((C)[0]), "+f"((C)[1]), "+f"((C)[2]), "+f"((C)[3])        \
                 : "r"((A)[0]), "r"((A)[1]), "r"((A)[2]), "r"((A)[3]),           \
                   "r"((B)[0]), "r"((B)[1]))

// ldmatrix x4: 4 8x8 bf16 matrices; lane i supplies row address per standard mapping.
__device__ __forceinline__ void ldm4(unsigned* r, unsigned a) {
    asm volatile("ldmatrix.sync.aligned.m8n8.x4.shared.b16 {%0,%1,%2,%3}, [%4];"
                 : "=r"(r[0]), "=r"(r[1]), "=r"(r[2]), "=r"(r[3]) : "r"(a));
}

__device__ __forceinline__ float ex2f(float x) {
    float r;
    asm("ex2.approx.ftz.f32 %0, %1;" : "=f"(r) : "f"(x));
    return r;
}

__device__ __forceinline__ void cp16(unsigned s, const void* g) {
    asm volatile("cp.async.ca.shared.global [%0], [%1], 16;" :: "r"(s), "l"(g));
}

__device__ __forceinline__ unsigned smem_u32(const void* p) {
    return (unsigned)__cvta_generic_to_shared(p);
}

__device__ __forceinline__ void pack_hilo(float f0, float f1, unsigned& h, unsigned& l) {
    __nv_bfloat162 hb = __floats2bfloat162_rn(f0, f1);
    float r0 = f0 - __bfloat162float(hb.x);
    float r1 = f1 - __bfloat162float(hb.y);
    __nv_bfloat162 lb = __floats2bfloat162_rn(r0, r1);
    h = *reinterpret_cast<unsigned*>(&hb);
    l = *reinterpret_cast<unsigned*>(&lb);
}

// ---------------------------------------------------------------------------
// Split kernels: fp32 -> bf16 hi + bf16 lo
// ---------------------------------------------------------------------------
__device__ __forceinline__ void split4(const float4 v, __nv_bfloat16* hi, __nv_bfloat16* lo, int i4) {
    float vs[4] = {v.x, v.y, v.z, v.w};
    unsigned hp[2], lp[2];
#pragma unroll
    for (int p = 0; p < 2; p++) pack_hilo(vs[2 * p], vs[2 * p + 1], hp[p], lp[p]);
    reinterpret_cast<uint2*>(hi)[i4] = make_uint2(hp[0], hp[1]);
    reinterpret_cast<uint2*>(lo)[i4] = make_uint2(lp[0], lp[1]);
}

__global__ void __launch_bounds__(256) split_x(const float* __restrict__ src) {
    int t = blockIdx.x * 256 + threadIdx.x;
    split4(reinterpret_cast<const float4*>(src)[t], g_xhi, g_xlo, t);
}
__global__ void __launch_bounds__(256) split_w(const float* __restrict__ src) {
    int t = blockIdx.x * 256 + threadIdx.x;
    split4(reinterpret_cast<const float4*>(src)[t], g_whi, g_wlo, t);
}

// ---------------------------------------------------------------------------
// Kernel 1: QKV projection GEMM (bf16x3 mma.sync + ldmatrix).
// CTA tile 128(M) x 64(N), BK=32, 8 warps (4 x 2), warp tile 32x32.
// ---------------------------------------------------------------------------
#define BK 32
#define KPAD 40

__global__ void __launch_bounds__(256) qkv_gemm_tc() {
    __shared__ __align__(16) __nv_bfloat16 sAhi[128][KPAD];
    __shared__ __align__(16) __nv_bfloat16 sAlo[128][KPAD];
    __shared__ __align__(16) __nv_bfloat16 sBhi[64][KPAD];
    __shared__ __align__(16) __nv_bfloat16 sBlo[64][KPAD];

    const int tid   = threadIdx.x;
    const int wid   = tid >> 5;
    const int lane  = tid & 31;
    const int warpM = wid >> 1;
    const int warpN = wid & 1;
    const int r0    = blockIdx.y * 128;
    const int e0    = blockIdx.x * 64;

    const int fr = lane >> 2;
    const int fc = (lane & 3) * 2;

    // ldmatrix lane-address components
    const int lrA = lane & 15;                              // A: row within 16
    const int lcA = (lane >> 4) << 3;                       // A: col 0 or 8
    const int lrB = (lane & 7) + ((lane >> 4) << 3);        // B: row within 16
    const int lcB = ((lane >> 3) & 1) << 3;                 // B: col 0 or 8

    const unsigned uAhi = smem_u32(sAhi), uAlo = smem_u32(sAlo);
    const unsigned uBhi = smem_u32(sBhi), uBlo = smem_u32(sBlo);

    const int mA = tid >> 2;
    const int kc = (tid & 3) * 8;

    const __nv_bfloat16* pXh = g_xhi + (size_t)(r0 + mA) * DMODEL + kc;
    const __nv_bfloat16* pXl = g_xlo + (size_t)(r0 + mA) * DMODEL + kc;
    const __nv_bfloat16* pWh = g_whi + (size_t)(e0 + mA) * DMODEL + kc;
    const __nv_bfloat16* pWl = g_wlo + (size_t)(e0 + mA) * DMODEL + kc;

    float acc[2][4][4] = {};

    uint4 pah0, pah1, pal0, pal1, pbh, pbl;
#define LOAD_TILES(K0)                                                               \
    do {                                                                             \
        pah0 = *reinterpret_cast<const uint4*>(pXh + (K0));                          \
        pah1 = *reinterpret_cast<const uint4*>(pXh + (K0) + 64 * DMODEL);            \
        pal0 = *reinterpret_cast<const uint4*>(pXl + (K0));                          \
        pal1 = *reinterpret_cast<const uint4*>(pXl + (K0) + 64 * DMODEL);            \
        pbh  = *reinterpret_cast<const uint4*>(pWh + (K0));                          \
        pbl  = *reinterpret_cast<const uint4*>(pWl + (K0));                          \
    } while (0)

    LOAD_TILES(0);

    for (int kt = 0; kt < DMODEL / BK; kt++) {
        __syncthreads();
        *reinterpret_cast<uint4*>(&sAhi[mA][kc])      = pah0;
        *reinterpret_cast<uint4*>(&sAhi[mA + 64][kc]) = pah1;
        *reinterpret_cast<uint4*>(&sAlo[mA][kc])      = pal0;
        *reinterpret_cast<uint4*>(&sAlo[mA + 64][kc]) = pal1;
        *reinterpret_cast<uint4*>(&sBhi[mA][kc])      = pbh;
        *reinterpret_cast<uint4*>(&sBlo[mA][kc])      = pbl;
        __syncthreads();

        if (kt + 1 < DMODEL / BK) LOAD_TILES((kt + 1) * BK);

#pragma unroll
        for (int ks = 0; ks < BK; ks += 16) {
            unsigned ahi[2][4], alo[2][4], bhi[2][4], blo[2][4];
#pragma unroll
            for (int am = 0; am < 2; am++) {
                const unsigned ao = (unsigned)(((warpM * 32 + am * 16 + lrA) * KPAD + ks + lcA) * 2);
                ldm4(ahi[am], uAhi + ao);
                ldm4(alo[am], uAlo + ao);
            }
#pragma unroll
            for (int g4 = 0; g4 < 2; g4++) {
                const unsigned bo = (unsigned)(((warpN * 32 + g4 * 16 + lrB) * KPAD + ks + lcB) * 2);
                ldm4(bhi[g4], uBhi + bo);
                ldm4(blo[g4], uBlo + bo);
            }
#pragma unroll
            for (int am = 0; am < 2; am++)
#pragma unroll
                for (int bn = 0; bn < 4; bn++) {
                    const unsigned* bh = &bhi[bn >> 1][(bn & 1) * 2];
                    const unsigned* bl = &blo[bn >> 1][(bn & 1) * 2];
                    MMA_BF16(acc[am][bn], ahi[am], bh);
                    MMA_BF16(acc[am][bn], ahi[am], bl);
                    MMA_BF16(acc[am][bn], alo[am], bh);
                }
        }
    }

#pragma unroll
    for (int am = 0; am < 2; am++)
#pragma unroll
        for (int bn = 0; bn < 4; bn++) {
            const int row = r0 + warpM * 32 + am * 16 + fr;
            const int col = e0 + warpN * 32 + bn * 8 + fc;
            *reinterpret_cast<float2*>(&g_qkv[(size_t)row * E3 + col]) =
                make_float2(acc[am][bn][0], acc[am][bn][1]);
            *reinterpret_cast<float2*>(&g_qkv[(size_t)(row + 8) * E3 + col]) =
                make_float2(acc[am][bn][2], acc[am][bn][3]);
        }
}

// ---------------------------------------------------------------------------
// Kernel 2: rope + split for Q and K -> bf16 hi/lo, layout [b][h][l][d].
// ---------------------------------------------------------------------------
#define QSCALE 0.1803368801111243f   // 0.125 * log2(e)

__global__ void __launch_bounds__(256) prep_qk() {
    const int t   = blockIdx.x * 256 + threadIdx.x;
    const int j   = t & 15;
    const int sqk = (t >> 4) & 1;
    const int h   = (t >> 5) & 15;
    const int r   = t >> 9;
    const int l   = r >> 1;
    const int b   = r & 1;

    const float* base = g_qkv + (size_t)r * E3 + h * 192 + sqk * 64;
    float x0 = base[j];
    float x1 = base[j + 16];
    float p0 = base[j + 32];
    float p1 = base[j + 48];

    float ang = (float)l * c_theta[j];
    float sn, cs;
    sincosf(ang, &sn, &cs);
    float y0 = x0 * cs - x1 * sn;
    float y1 = x1 * cs + x0 * sn;

    const float sc = sqk ? 1.0f : QSCALE;
    y0 *= sc; y1 *= sc; p0 *= sc; p1 *= sc;

    const size_t dst = ((size_t)(b * NHEADS + h) * L_SEQ + l) * DK;
    __nv_bfloat16* dh = (sqk ? g_khi : g_qhi) + dst;
    __nv_bfloat16* dl = (sqk ? g_klo : g_qlo) + dst;

    float vals[4] = {y0, y1, p0, p1};
    int   ds[4]   = {j, j + 16, j + 32, j + 48};
#pragma unroll
    for (int i = 0; i < 4; i++) {
        __nv_bfloat16 hi = __float2bfloat16_rn(vals[i]);
        dh[ds[i]] = hi;
        dl[ds[i]] = __float2bfloat16_rn(vals[i] - __bfloat162float(hi));
    }
}

// ---------------------------------------------------------------------------
// Kernel 3: V transpose + split -> bf16 hi/lo, layout [b][h][d][l].
// ---------------------------------------------------------------------------
__global__ void __launch_bounds__(128) prep_v() {
    __shared__ float s[64][68];
    const int tile = blockIdx.x, h = blockIdx.y, b = blockIdx.z;
    const int tid = threadIdx.x;

#pragma unroll
    for (int i = 0; i < 8; i++) {
        int id  = i * 128 + tid;
        int row = id >> 4;
        int c4  = id & 15;
        const float* g = g_qkv + (size_t)((tile * 64 + row) * 2 + b) * E3 + h * 192 + 128 + c4 * 4;
        float4 v = *reinterpret_cast<const float4*>(g);
        s[row][c4 * 4 + 0] = v.x; s[row][c4 * 4 + 1] = v.y;
        s[row][c4 * 4 + 2] = v.z; s[row][c4 * 4 + 3] = v.w;
    }
    __syncthreads();

    const int d = tid & 63, part = tid >> 6;
    const size_t ob = ((size_t)(b * NHEADS + h) * DK + d) * L_SEQ + tile * 64 + part * 32;

#pragma unroll
    for (int kc = 0; kc < 4; kc++) {
        unsigned hw[4], lw[4];
#pragma unroll
        for (int p = 0; p < 4; p++) {
            float v0 = s[part * 32 + kc * 8 + p * 2 + 0][d];
            float v1 = s[part * 32 + kc * 8 + p * 2 + 1][d];
            pack_hilo(v0, v1, hw[p], lw[p]);
        }
        *reinterpret_cast<uint4*>(g_vhi + ob + kc * 8) = make_uint4(hw[0], hw[1], hw[2], hw[3]);
        *reinterpret_cast<uint4*>(g_vlo + ob + kc * 8) = make_uint4(lw[0], lw[1], lw[2], lw[3]);
    }
}

// ---------------------------------------------------------------------------
// Kernel 4: tensor-core flash attention (bf16x3 mma.sync + ldmatrix).
// CTA = 128 queries x (h,b). 4 warps, 32 rows each. KV tiles of 64,
// double-buffered cp.async. P in registers (C->A fragment reuse).
// ---------------------------------------------------------------------------
#define ATTN_SMEM_BYTES ((18432 + 2 * 18432) * 2)

__global__ void __launch_bounds__(128) attn_tc(float* __restrict__ out) {
    extern __shared__ __align__(16) __nv_bfloat16 sm[];
    const unsigned smem_base = smem_u32(sm);

    const int tid  = threadIdx.x;
    const int w    = tid >> 5;
    const int lane = tid & 31;
    const int g    = lane >> 2;
    const int tg   = lane & 3;

    // ldmatrix lane-address components
    const int lrA = lane & 15;
    const int lcA = (lane >> 4) << 3;
    const int lrB = (lane & 7) + ((lane >> 4) << 3);
    const int lcB = ((lane >> 3) & 1) << 3;

    const int q0 = blockIdx.x * 128;
    const int h  = blockIdx.y;
    const int b  = blockIdx.z;
    const int hb = b * NHEADS + h;

    const size_t qkbase = (size_t)hb * L_SEQ * DK;
    const size_t vbase  = (size_t)hb * DK * L_SEQ;

#pragma unroll
    for (int i = 0; i < 16; i++) {
        int id  = i * 128 + tid;
        int rid = (id >> 3) & 127;
        int ch  = id & 7;
        const __nv_bfloat16* gp = (i < 8 ? g_qhi : g_qlo) + qkbase + (size_t)(q0 + rid) * DK + ch * 8;
        unsigned sp = smem_base + ((i < 8 ? 0 : 9216) + rid * 72 + ch * 8) * 2;
        cp16(sp, gp);
    }

#define ISSUE_TILE(T, BUF)                                                            \
    do {                                                                              \
        _Pragma("unroll")                                                             \
        for (int i = 0; i < 16; i++) {                                                \
            int id  = i * 128 + tid;                                                  \
            int arr = i >> 2;                                                         \
            int rid = (id >> 3) & 63;                                                 \
            int ch  = id & 7;                                                         \
            const __nv_bfloat16* gp;                                                  \
            if (arr == 0)      gp = g_khi + qkbase + (size_t)((T) * 64 + rid) * DK + ch * 8; \
            else if (arr == 1) gp = g_klo + qkbase + (size_t)((T) * 64 + rid) * DK + ch * 8; \
            else if (arr == 2) gp = g_vhi + vbase + (size_t)rid * L_SEQ + (T) * 64 + ch * 8; \
            else               gp = g_vlo + vbase + (size_t)rid * L_SEQ + (T) * 64 + ch * 8; \
            unsigned sp = smem_base + (18432 + (BUF) * 18432 + arr * 4608 + rid * 72 + ch * 8) * 2; \
            cp16(sp, gp);                                                             \
        }                                                                             \
    } while (0)

    ISSUE_TILE(0, 0);
    asm volatile("cp.async.commit_group;");

    float o[2][8][4] = {};
    float mrow[2][2] = {{-1e30f, -1e30f}, {-1e30f, -1e30f}};
    float lrow[2][2] = {};

    const int rb0 = w * 32;

    for (int t = 0; t < 32; t++) {
        const int cur = t & 1;
        if (t < 31) {
            ISSUE_TILE(t + 1, cur ^ 1);
            asm volatile("cp.async.commit_group;");
            asm volatile("cp.async.wait_group 1;");
        } else {
            asm volatile("cp.async.wait_group 0;");
        }
        __syncthreads();

        const unsigned uQh = smem_base;
        const unsigned uQl = smem_base + 9216 * 2;
        const unsigned uKh = smem_base + (18432 + cur * 18432) * 2;
        const unsigned uKl = uKh + 4608 * 2;
        const unsigned uVh = uKh + 9216 * 2;
        const unsigned uVl = uKh + 13824 * 2;

        // ---- S = Q K^T (bf16x3) ----
        float s[2][8][4] = {};
#pragma unroll
        for (int kf = 0; kf < 4; kf++) {
            unsigned ah[2][4], al[2][4], kh[4][4], kl[4][4];
#pragma unroll
            for (int mf = 0; mf < 2; mf++) {
                const unsigned ao = (unsigned)(((rb0 + mf * 16 + lrA) * 72 + kf * 16 + lcA) * 2);
                ldm4(ah[mf], uQh + ao);
                ldm4(al[mf], uQl + ao);
            }
#pragma unroll
            for (int g4 = 0; g4 < 4; g4++) {
                const unsigned bo = (unsigned)(((g4 * 16 + lrB) * 72 + kf * 16 + lcB) * 2);
                ldm4(kh[g4], uKh + bo);
                ldm4(kl[g4], uKl + bo);
            }
#pragma unroll
            for (int nf = 0; nf < 8; nf++) {
                const unsigned* bh = &kh[nf >> 1][(nf & 1) * 2];
                const unsigned* bl = &kl[nf >> 1][(nf & 1) * 2];
#pragma unroll
                for (int mf = 0; mf < 2; mf++) {
                    MMA_BF16(s[mf][nf], ah[mf], bh);
                    MMA_BF16(s[mf][nf], ah[mf], bl);
                    MMA_BF16(s[mf][nf], al[mf], bh);
                }
            }
        }

        // ---- online softmax (log2 domain) ----
        unsigned ph[2][4][4], pl[2][4][4];
#pragma unroll
        for (int mf = 0; mf < 2; mf++) {
            float mx0 = -1e30f, mx1 = -1e30f;
#pragma unroll
            for (int nf = 0; nf < 8; nf++) {
                mx0 = fmaxf(mx0, fmaxf(s[mf][nf][0], s[mf][nf][1]));
                mx1 = fmaxf(mx1, fmaxf(s[mf][nf][2], s[mf][nf][3]));
            }
            mx0 = fmaxf(mx0, __shfl_xor_sync(0xffffffffu, mx0, 1));
            mx0 = fmaxf(mx0, __shfl_xor_sync(0xffffffffu, mx0, 2));
            mx1 = fmaxf(mx1, __shfl_xor_sync(0xffffffffu, mx1, 1));
            mx1 = fmaxf(mx1, __shfl_xor_sync(0xffffffffu, mx1, 2));

            float mn0 = fmaxf(mrow[mf][0], mx0);
            float mn1 = fmaxf(mrow[mf][1], mx1);
            float sc0 = ex2f(mrow[mf][0] - mn0);
            float sc1 = ex2f(mrow[mf][1] - mn1);
            mrow[mf][0] = mn0;
            mrow[mf][1] = mn1;

            float rs0 = 0.f, rs1 = 0.f;
#pragma unroll
            for (int nf = 0; nf < 8; nf++) {
                s[mf][nf][0] = ex2f(s[mf][nf][0] - mn0);
                s[mf][nf][1] = ex2f(s[mf][nf][1] - mn0);
                s[mf][nf][2] = ex2f(s[mf][nf][2] - mn1);
                s[mf][nf][3] = ex2f(s[mf][nf][3] - mn1);
                rs0 += s[mf][nf][0] + s[mf][nf][1];
                rs1 += s[mf][nf][2] + s[mf][nf][3];
            }
            rs0 += __shfl_xor_sync(0xffffffffu, rs0, 1);
            rs0 += __shfl_xor_sync(0xffffffffu, rs0, 2);
            rs1 += __shfl_xor_sync(0xffffffffu, rs1, 1);
            rs1 += __shfl_xor_sync(0xffffffffu, rs1, 2);
            lrow[mf][0] = lrow[mf][0] * sc0 + rs0;
            lrow[mf][1] = lrow[mf][1] * sc1 + rs1;

#pragma unroll
            for (int nf = 0; nf < 8; nf++) {
                o[mf][nf][0] *= sc0; o[mf][nf][1] *= sc0;
                o[mf][nf][2] *= sc1; o[mf][nf][3] *= sc1;
            }

#pragma unroll
            for (int kf = 0; kf < 4; kf++) {
                const int n0 = 2 * kf, n1 = 2 * kf + 1;
                pack_hilo(s[mf][n0][0], s[mf][n0][1], ph[mf][kf][0], pl[mf][kf][0]);
                pack_hilo(s[mf][n0][2], s[mf][n0][3], ph[mf][kf][1], pl[mf][kf][1]);
                pack_hilo(s[mf][n1][0], s[mf][n1][1], ph[mf][kf][2], pl[mf][kf][2]);
                pack_hilo(s[mf][n1][2], s[mf][n1][3], ph[mf][kf][3], pl[mf][kf][3]);
            }
        }

        // ---- O += P V (bf16x3) ----
#pragma unroll
        for (int kf = 0; kf < 4; kf++) {
            unsigned vh[4][4], vl[4][4];
#pragma unroll
            for (int g4 = 0; g4 < 4; g4++) {
                const unsigned bo = (unsigned)(((g4 * 16 + lrB) * 72 + kf * 16 + lcB) * 2);
                ldm4(vh[g4], uVh + bo);
                ldm4(vl[g4], uVl + bo);
            }
#pragma unroll
            for (int nf = 0; nf < 8; nf++) {
                const unsigned* bh = &vh[nf >> 1][(nf & 1) * 2];
                const unsigned* bl = &vl[nf >> 1][(nf & 1) * 2];
#pragma unroll
                for (int mf = 0; mf < 2; mf++) {
                    MMA_BF16(o[mf][nf], ph[mf][kf], bh);
                    MMA_BF16(o[mf][nf], pl[mf][kf], bh);
                    MMA_BF16(o[mf][nf], ph[mf][kf], bl);
                }
            }
        }
        __syncthreads();
    }

    // ---- epilogue: out[l][b][h*64 + d] ----
#pragma unroll
    for (int mf = 0; mf < 2; mf++) {
        const float inv0 = 1.0f / lrow[mf][0];
        const float inv1 = 1.0f / lrow[mf][1];
        const int r0 = q0 + rb0 + mf * 16 + g;
#pragma unroll
        for (int nf = 0; nf < 8; nf++) {
            const int col = h * 64 + nf * 8 + tg * 2;
            *reinterpret_cast<float2*>(out + (size_t)(r0 * 2 + b) * DMODEL + col) =
                make_float2(o[mf][nf][0] * inv0, o[mf][nf][1] * inv0);
            *reinterpret_cast<float2*>(out + (size_t)((r0 + 8) * 2 + b) * DMODEL + col) =
                make_float2(o[mf][nf][2] * inv1, o[mf][nf][3] * inv1);
        }
    }
}

// ---------------------------------------------------------------------------
extern "C" void kernel_launch(void* const* d_in, const int* in_sizes, int n_in,
                              void* d_out, int out_size) {
    const float* x = (const float*)d_in[0];
    const float* w = (const float*)d_in[1];
    if (n_in >= 2 && in_sizes[0] == E3 * DMODEL && in_sizes[1] == NROWS * DMODEL) {
        const float* t = x; x = w; w = t;
    }
    float* out = (float*)d_out;

    static bool attr_set = false;
    if (!attr_set) {
        cudaFuncSetAttribute(attn_tc, cudaFuncAttributeMaxDynamicSharedMemorySize,
                             ATTN_SMEM_BYTES);
        attr_set = true;
    }

    split_x<<<(NROWS * DMODEL / 4) / 256, 256>>>(x);
    split_w<<<(E3 * DMODEL / 4) / 256, 256>>>(w);
    qkv_gemm_tc<<<dim3(E3 / 64, NROWS / 128), 256>>>();
    prep_qk<<<(NROWS * NHEADS * 2 * 16) / 256, 256>>>();
    prep_v<<<dim3(L_SEQ / 64, NHEADS, BATCH), 128>>>();
    attn_tc<<<dim3(L_SEQ / 128, NHEADS, BATCH), 128, ATTN_SMEM_BYTES>>>(out);
}

// round 7
// speedup vs baseline: 3.1980x; 1.0579x over previous
#include <cuda_runtime.h>
#include <cuda_bf16.h>

#define L_SEQ  2048
#define BATCH  2
#define DMODEL 1024
#define NHEADS 16
#define DK     64
#define E3     3072
#define NROWS  4096

// fp32 QKV projection scratch: [NROWS][E3], row r = l*BATCH + b, col e = h*192 + {q,k,v}
__device__ float g_qkv[NROWS * E3];

// bf16 hi/lo splits of X and W for the projection GEMM
__device__ __align__(16) __nv_bfloat16 g_xhi[NROWS * DMODEL];
__device__ __align__(16) __nv_bfloat16 g_xlo[NROWS * DMODEL];
__device__ __align__(16) __nv_bfloat16 g_whi[E3 * DMODEL];
__device__ __align__(16) __nv_bfloat16 g_wlo[E3 * DMODEL];

// Attention operand buffers (bf16 hi/lo).
// Q,K: [b][h][l][d] (rope applied; Q pre-scaled by 0.125*log2e). V: [b][h][d][l].
#define QKV_ELEMS (BATCH * NHEADS * L_SEQ * DK)
__device__ __align__(16) __nv_bfloat16 g_qhi[QKV_ELEMS];
__device__ __align__(16) __nv_bfloat16 g_qlo[QKV_ELEMS];
__device__ __align__(16) __nv_bfloat16 g_khi[QKV_ELEMS];
__device__ __align__(16) __nv_bfloat16 g_klo[QKV_ELEMS];
__device__ __align__(16) __nv_bfloat16 g_vhi[QKV_ELEMS];
__device__ __align__(16) __nv_bfloat16 g_vlo[QKV_ELEMS];

__constant__ float c_theta[16] = {
    1.0f,                     0.5623413251903491f,     0.31622776601683794f,   0.17782794100389228f,
    0.1f,                     0.05623413251903491f,    0.031622776601683794f,  0.017782794100389228f,
    0.01f,                    0.005623413251903491f,   0.0031622776601683794f, 0.0017782794100389228f,
    0.001f,                   0.0005623413251903491f,  0.00031622776601683794f,0.00017782794100389227f
};

// ---------------------------------------------------------------------------
// Helpers
// ---------------------------------------------------------------------------
#define MMA_BF16(C, A, B)                                                        \
    asm volatile("mma.sync.aligned.m16n8k16.row.col.f32.bf16.bf16.f32 "          \
                 "{%0,%1,%2,%3}, {%4,%5,%6,%7}, {%8,%9}, {%0,%1,%2,%3};"         \
                 : "+f"((C)[0]), "+f"((C)[1]), "+f"((C)[2]), "+f"((C)[3])        \
                 : "r"((A)[0]), "r"((A)[1]), "r"((A)[2]), "r"((A)[3]),           \
                   "r"((B)[0]), "r"((B)[1]))

__device__ __forceinline__ void ldm4(unsigned* r, unsigned a) {
    asm volatile("ldmatrix.sync.aligned.m8n8.x4.shared.b16 {%0,%1,%2,%3}, [%4];"
                 : "=r"(r[0]), "=r"(r[1]), "=r"(r[2]), "=r"(r[3]) : "r"(a));
}

__device__ __forceinline__ float ex2f(float x) {
    float r;
    asm("ex2.approx.ftz.f32 %0, %1;" : "=f"(r) : "f"(x));
    return r;
}

__device__ __forceinline__ void cp16(unsigned s, const void* g) {
    asm volatile("cp.async.ca.shared.global [%0], [%1], 16;" :: "r"(s), "l"(g));
}

__device__ __forceinline__ unsigned smem_u32(const void* p) {
    return (unsigned)__cvta_generic_to_shared(p);
}

__device__ __forceinline__ void pack_hilo(float f0, float f1, unsigned& h, unsigned& l) {
    __nv_bfloat162 hb = __floats2bfloat162_rn(f0, f1);
    float r0 = f0 - __bfloat162float(hb.x);
    float r1 = f1 - __bfloat162float(hb.y);
    __nv_bfloat162 lb = __floats2bfloat162_rn(r0, r1);
    h = *reinterpret_cast<unsigned*>(&hb);
    l = *reinterpret_cast<unsigned*>(&lb);
}

// ---------------------------------------------------------------------------
// Split kernels: fp32 -> bf16 hi + bf16 lo
// ---------------------------------------------------------------------------
__device__ __forceinline__ void split4(const float4 v, __nv_bfloat16* hi, __nv_bfloat16* lo, int i4) {
    float vs[4] = {v.x, v.y, v.z, v.w};
    unsigned hp[2], lp[2];
#pragma unroll
    for (int p = 0; p < 2; p++) pack_hilo(vs[2 * p], vs[2 * p + 1], hp[p], lp[p]);
    reinterpret_cast<uint2*>(hi)[i4] = make_uint2(hp[0], hp[1]);
    reinterpret_cast<uint2*>(lo)[i4] = make_uint2(lp[0], lp[1]);
}

__global__ void __launch_bounds__(256) split_x(const float* __restrict__ src) {
    int t = blockIdx.x * 256 + threadIdx.x;
    split4(reinterpret_cast<const float4*>(src)[t], g_xhi, g_xlo, t);
}
__global__ void __launch_bounds__(256) split_w(const float* __restrict__ src) {
    int t = blockIdx.x * 256 + threadIdx.x;
    split4(reinterpret_cast<const float4*>(src)[t], g_whi, g_wlo, t);
}

// ---------------------------------------------------------------------------
// Kernel 1: QKV projection GEMM (bf16x3 mma.sync + ldmatrix + cp.async).
// CTA tile 128(M) x 128(N), BK=32, 8 warps (4M x 2N), warp tile 32x64.
// 2-stage cp.async double buffer. smem/stage: 4 arrays x 128 x 40 bf16 = 40KB.
// ---------------------------------------------------------------------------
#define KPAD 40
#define ARR_B  (128 * KPAD * 2)            // bytes per array (10240)
#define STG_B  (4 * ARR_B)                 // bytes per stage (40960)
#define QKV_SMEM (2 * STG_B)

// Fill one stage: arrays {Ahi, Alo, Bhi, Blo}, rows 128, BK=32 cols.
#define G_ISSUE(KT, ST)                                                               \
    do {                                                                              \
        const int _k0 = (KT) * 32;                                                    \
        _Pragma("unroll")                                                             \
        for (int _arr = 0; _arr < 4; _arr++) {                                        \
            _Pragma("unroll")                                                         \
            for (int _rep = 0; _rep < 2; _rep++) {                                    \
                int _sub = _rep * 256 + tid;                                          \
                int _row = _sub >> 2;                                                 \
                int _ch  = _sub & 3;                                                  \
                unsigned _sp = smem0 + (ST) * STG_B + _arr * ARR_B + _row * (KPAD*2) + _ch * 16; \
                const __nv_bfloat16* _gp;                                             \
                if      (_arr == 0) _gp = g_xhi + (size_t)(r0 + _row) * DMODEL + _k0 + _ch * 8; \
                else if (_arr == 1) _gp = g_xlo + (size_t)(r0 + _row) * DMODEL + _k0 + _ch * 8; \
                else if (_arr == 2) _gp = g_whi + (size_t)(e0 + _row) * DMODEL + _k0 + _ch * 8; \
                else                _gp = g_wlo + (size_t)(e0 + _row) * DMODEL + _k0 + _ch * 8; \
                cp16(_sp, _gp);                                                       \
            }                                                                         \
        }                                                                             \
        asm volatile("cp.async.commit_group;");                                       \
    } while (0)

__global__ void __launch_bounds__(256) qkv_gemm_tc() {
    extern __shared__ __align__(16) char qsm[];
    const unsigned smem0 = smem_u32(qsm);

    const int tid   = threadIdx.x;
    const int wid   = tid >> 5;
    const int lane  = tid & 31;
    const int warpM = wid >> 1;            // 0..3 -> m * 32
    const int warpN = wid & 1;             // 0..1 -> n * 64
    const int r0    = blockIdx.y * 128;
    const int e0    = blockIdx.x * 128;

    const int fr = lane >> 2;
    const int fc = (lane & 3) * 2;

    // ldmatrix lane-address components
    const int lrA = lane & 15;
    const int lcA = (lane >> 4) << 3;
    const int lrB = (lane & 7) + ((lane >> 4) << 3);
    const int lcB = ((lane >> 3) & 1) << 3;

    float acc[2][8][4] = {};

    G_ISSUE(0, 0);
    G_ISSUE(1, 1);

    for (int kt = 0; kt < 32; kt++) {
        if (kt < 31) asm volatile("cp.async.wait_group 1;");
        else         asm volatile("cp.async.wait_group 0;");
        __syncthreads();

        const unsigned uA_hi = smem0 + (kt & 1) * STG_B;
        const unsigned uA_lo = uA_hi + ARR_B;
        const unsigned uB_hi = uA_hi + 2 * ARR_B;
        const unsigned uB_lo = uA_hi + 3 * ARR_B;

#pragma unroll
        for (int ks = 0; ks < 32; ks += 16) {
            unsigned ahi[2][4], alo[2][4], bhi[4][4], blo[4][4];
#pragma unroll
            for (int mf = 0; mf < 2; mf++) {
                const unsigned ao = (unsigned)(((warpM * 32 + mf * 16 + lrA) * KPAD + ks + lcA) * 2);
                ldm4(ahi[mf], uA_hi + ao);
                ldm4(alo[mf], uA_lo + ao);
            }
#pragma unroll
            for (int g4 = 0; g4 < 4; g4++) {
                const unsigned bo = (unsigned)(((warpN * 64 + g4 * 16 + lrB) * KPAD + ks + lcB) * 2);
                ldm4(bhi[g4], uB_hi + bo);
                ldm4(blo[g4], uB_lo + bo);
            }
#pragma unroll
            for (int mf = 0; mf < 2; mf++)
#pragma unroll
                for (int nf = 0; nf < 8; nf++) {
                    const unsigned* bh = &bhi[nf >> 1][(nf & 1) * 2];
                    const unsigned* bl = &blo[nf >> 1][(nf & 1) * 2];
                    MMA_BF16(acc[mf][nf], ahi[mf], bh);
                    MMA_BF16(acc[mf][nf], ahi[mf], bl);
                    MMA_BF16(acc[mf][nf], alo[mf], bh);
                }
        }
        __syncthreads();
        if (kt + 2 < 32) G_ISSUE(kt + 2, kt & 1);
    }

    // Epilogue
#pragma unroll
    for (int mf = 0; mf < 2; mf++)
#pragma unroll
        for (int nf = 0; nf < 8; nf++) {
            const int row = r0 + warpM * 32 + mf * 16 + fr;
            const int col = e0 + warpN * 64 + nf * 8 + fc;
            *reinterpret_cast<float2*>(&g_qkv[(size_t)row * E3 + col]) =
                make_float2(acc[mf][nf][0], acc[mf][nf][1]);
            *reinterpret_cast<float2*>(&g_qkv[(size_t)(row + 8) * E3 + col]) =
                make_float2(acc[mf][nf][2], acc[mf][nf][3]);
        }
}

// ---------------------------------------------------------------------------
// Kernel 2: rope + split for Q and K -> bf16 hi/lo, layout [b][h][l][d].
// ---------------------------------------------------------------------------
#define QSCALE 0.1803368801111243f   // 0.125 * log2(e)

__global__ void __launch_bounds__(256) prep_qk() {
    const int t   = blockIdx.x * 256 + threadIdx.x;
    const int j   = t & 15;
    const int sqk = (t >> 4) & 1;
    const int h   = (t >> 5) & 15;
    const int r   = t >> 9;
    const int l   = r >> 1;
    const int b   = r & 1;

    const float* base = g_qkv + (size_t)r * E3 + h * 192 + sqk * 64;
    float x0 = base[j];
    float x1 = base[j + 16];
    float p0 = base[j + 32];
    float p1 = base[j + 48];

    float ang = (float)l * c_theta[j];
    float sn, cs;
    sincosf(ang, &sn, &cs);
    float y0 = x0 * cs - x1 * sn;
    float y1 = x1 * cs + x0 * sn;

    const float sc = sqk ? 1.0f : QSCALE;
    y0 *= sc; y1 *= sc; p0 *= sc; p1 *= sc;

    const size_t dst = ((size_t)(b * NHEADS + h) * L_SEQ + l) * DK;
    __nv_bfloat16* dh = (sqk ? g_khi : g_qhi) + dst;
    __nv_bfloat16* dl = (sqk ? g_klo : g_qlo) + dst;

    float vals[4] = {y0, y1, p0, p1};
    int   ds[4]   = {j, j + 16, j + 32, j + 48};
#pragma unroll
    for (int i = 0; i < 4; i++) {
        __nv_bfloat16 hi = __float2bfloat16_rn(vals[i]);
        dh[ds[i]] = hi;
        dl[ds[i]] = __float2bfloat16_rn(vals[i] - __bfloat162float(hi));
    }
}

// ---------------------------------------------------------------------------
// Kernel 3: V transpose + split -> bf16 hi/lo, layout [b][h][d][l].
// ---------------------------------------------------------------------------
__global__ void __launch_bounds__(128) prep_v() {
    __shared__ float s[64][68];
    const int tile = blockIdx.x, h = blockIdx.y, b = blockIdx.z;
    const int tid = threadIdx.x;

#pragma unroll
    for (int i = 0; i < 8; i++) {
        int id  = i * 128 + tid;
        int row = id >> 4;
        int c4  = id & 15;
        const float* g = g_qkv + (size_t)((tile * 64 + row) * 2 + b) * E3 + h * 192 + 128 + c4 * 4;
        float4 v = *reinterpret_cast<const float4*>(g);
        s[row][c4 * 4 + 0] = v.x; s[row][c4 * 4 + 1] = v.y;
        s[row][c4 * 4 + 2] = v.z; s[row][c4 * 4 + 3] = v.w;
    }
    __syncthreads();

    const int d = tid & 63, part = tid >> 6;
    const size_t ob = ((size_t)(b * NHEADS + h) * DK + d) * L_SEQ + tile * 64 + part * 32;

#pragma unroll
    for (int kc = 0; kc < 4; kc++) {
        unsigned hw[4], lw[4];
#pragma unroll
        for (int p = 0; p < 4; p++) {
            float v0 = s[part * 32 + kc * 8 + p * 2 + 0][d];
            float v1 = s[part * 32 + kc * 8 + p * 2 + 1][d];
            pack_hilo(v0, v1, hw[p], lw[p]);
        }
        *reinterpret_cast<uint4*>(g_vhi + ob + kc * 8) = make_uint4(hw[0], hw[1], hw[2], hw[3]);
        *reinterpret_cast<uint4*>(g_vlo + ob + kc * 8) = make_uint4(lw[0], lw[1], lw[2], lw[3]);
    }
}

// ---------------------------------------------------------------------------
// Kernel 4: tensor-core flash attention (bf16x3 mma.sync + ldmatrix) — unchanged.
// ---------------------------------------------------------------------------
#define ATTN_SMEM_BYTES ((18432 + 2 * 18432) * 2)

__global__ void __launch_bounds__(128) attn_tc(float* __restrict__ out) {
    extern __shared__ __align__(16) __nv_bfloat16 sm[];
    const unsigned smem_base = smem_u32(sm);

    const int tid  = threadIdx.x;
    const int w    = tid >> 5;
    const int lane = tid & 31;
    const int g    = lane >> 2;
    const int tg   = lane & 3;

    const int lrA = lane & 15;
    const int lcA = (lane >> 4) << 3;
    const int lrB = (lane & 7) + ((lane >> 4) << 3);
    const int lcB = ((lane >> 3) & 1) << 3;

    const int q0 = blockIdx.x * 128;
    const int h  = blockIdx.y;
    const int b  = blockIdx.z;
    const int hb = b * NHEADS + h;

    const size_t qkbase = (size_t)hb * L_SEQ * DK;
    const size_t vbase  = (size_t)hb * DK * L_SEQ;

#pragma unroll
    for (int i = 0; i < 16; i++) {
        int id  = i * 128 + tid;
        int rid = (id >> 3) & 127;
        int ch  = id & 7;
        const __nv_bfloat16* gp = (i < 8 ? g_qhi : g_qlo) + qkbase + (size_t)(q0 + rid) * DK + ch * 8;
        unsigned sp = smem_base + ((i < 8 ? 0 : 9216) + rid * 72 + ch * 8) * 2;
        cp16(sp, gp);
    }

#define ISSUE_TILE(T, BUF)                                                            \
    do {                                                                              \
        _Pragma("unroll")                                                             \
        for (int i = 0; i < 16; i++) {                                                \
            int id  = i * 128 + tid;                                                  \
            int arr = i >> 2;                                                         \
            int rid = (id >> 3) & 63;                                                 \
            int ch  = id & 7;                                                         \
            const __nv_bfloat16* gp;                                                  \
            if (arr == 0)      gp = g_khi + qkbase + (size_t)((T) * 64 + rid) * DK + ch * 8; \
            else if (arr == 1) gp = g_klo + qkbase + (size_t)((T) * 64 + rid) * DK + ch * 8; \
            else if (arr == 2) gp = g_vhi + vbase + (size_t)rid * L_SEQ + (T) * 64 + ch * 8; \
            else               gp = g_vlo + vbase + (size_t)rid * L_SEQ + (T) * 64 + ch * 8; \
            unsigned sp = smem_base + (18432 + (BUF) * 18432 + arr * 4608 + rid * 72 + ch * 8) * 2; \
            cp16(sp, gp);                                                             \
        }                                                                             \
    } while (0)

    ISSUE_TILE(0, 0);
    asm volatile("cp.async.commit_group;");

    float o[2][8][4] = {};
    float mrow[2][2] = {{-1e30f, -1e30f}, {-1e30f, -1e30f}};
    float lrow[2][2] = {};

    const int rb0 = w * 32;

    for (int t = 0; t < 32; t++) {
        const int cur = t & 1;
        if (t < 31) {
            ISSUE_TILE(t + 1, cur ^ 1);
            asm volatile("cp.async.commit_group;");
            asm volatile("cp.async.wait_group 1;");
        } else {
            asm volatile("cp.async.wait_group 0;");
        }
        __syncthreads();

        const unsigned uQh = smem_base;
        const unsigned uQl = smem_base + 9216 * 2;
        const unsigned uKh = smem_base + (18432 + cur * 18432) * 2;
        const unsigned uKl = uKh + 4608 * 2;
        const unsigned uVh = uKh + 9216 * 2;
        const unsigned uVl = uKh + 13824 * 2;

        float s[2][8][4] = {};
#pragma unroll
        for (int kf = 0; kf < 4; kf++) {
            unsigned ah[2][4], al[2][4], kh[4][4], kl[4][4];
#pragma unroll
            for (int mf = 0; mf < 2; mf++) {
                const unsigned ao = (unsigned)(((rb0 + mf * 16 + lrA) * 72 + kf * 16 + lcA) * 2);
                ldm4(ah[mf], uQh + ao);
                ldm4(al[mf], uQl + ao);
            }
#pragma unroll
            for (int g4 = 0; g4 < 4; g4++) {
                const unsigned bo = (unsigned)(((g4 * 16 + lrB) * 72 + kf * 16 + lcB) * 2);
                ldm4(kh[g4], uKh + bo);
                ldm4(kl[g4], uKl + bo);
            }
#pragma unroll
            for (int nf = 0; nf < 8; nf++) {
                const unsigned* bh = &kh[nf >> 1][(nf & 1) * 2];
                const unsigned* bl = &kl[nf >> 1][(nf & 1) * 2];
#pragma unroll
                for (int mf = 0; mf < 2; mf++) {
                    MMA_BF16(s[mf][nf], ah[mf], bh);
                    MMA_BF16(s[mf][nf], ah[mf], bl);
                    MMA_BF16(s[mf][nf], al[mf], bh);
                }
            }
        }

        unsigned ph[2][4][4], pl[2][4][4];
#pragma unroll
        for (int mf = 0; mf < 2; mf++) {
            float mx0 = -1e30f, mx1 = -1e30f;
#pragma unroll
            for (int nf = 0; nf < 8; nf++) {
                mx0 = fmaxf(mx0, fmaxf(s[mf][nf][0], s[mf][nf][1]));
                mx1 = fmaxf(mx1, fmaxf(s[mf][nf][2], s[mf][nf][3]));
            }
            mx0 = fmaxf(mx0, __shfl_xor_sync(0xffffffffu, mx0, 1));
            mx0 = fmaxf(mx0, __shfl_xor_sync(0xffffffffu, mx0, 2));
            mx1 = fmaxf(mx1, __shfl_xor_sync(0xffffffffu, mx1, 1));
            mx1 = fmaxf(mx1, __shfl_xor_sync(0xffffffffu, mx1, 2));

            float mn0 = fmaxf(mrow[mf][0], mx0);
            float mn1 = fmaxf(mrow[mf][1], mx1);
            float sc0 = ex2f(mrow[mf][0] - mn0);
            float sc1 = ex2f(mrow[mf][1] - mn1);
            mrow[mf][0] = mn0;
            mrow[mf][1] = mn1;

            float rs0 = 0.f, rs1 = 0.f;
#pragma unroll
            for (int nf = 0; nf < 8; nf++) {
                s[mf][nf][0] = ex2f(s[mf][nf][0] - mn0);
                s[mf][nf][1] = ex2f(s[mf][nf][1] - mn0);
                s[mf][nf][2] = ex2f(s[mf][nf][2] - mn1);
                s[mf][nf][3] = ex2f(s[mf][nf][3] - mn1);
                rs0 += s[mf][nf][0] + s[mf][nf][1];
                rs1 += s[mf][nf][2] + s[mf][nf][3];
            }
            rs0 += __shfl_xor_sync(0xffffffffu, rs0, 1);
            rs0 += __shfl_xor_sync(0xffffffffu, rs0, 2);
            rs1 += __shfl_xor_sync(0xffffffffu, rs1, 1);
            rs1 += __shfl_xor_sync(0xffffffffu, rs1, 2);
            lrow[mf][0] = lrow[mf][0] * sc0 + rs0;
            lrow[mf][1] = lrow[mf][1] * sc1 + rs1;

#pragma unroll
            for (int nf = 0; nf < 8; nf++) {
                o[mf][nf][0] *= sc0; o[mf][nf][1] *= sc0;
                o[mf][nf][2] *= sc1; o[mf][nf][3] *= sc1;
            }

#pragma unroll
            for (int kf = 0; kf < 4; kf++) {
                const int n0 = 2 * kf, n1 = 2 * kf + 1;
                pack_hilo(s[mf][n0][0], s[mf][n0][1], ph[mf][kf][0], pl[mf][kf][0]);
                pack_hilo(s[mf][n0][2], s[mf][n0][3], ph[mf][kf][1], pl[mf][kf][1]);
                pack_hilo(s[mf][n1][0], s[mf][n1][1], ph[mf][kf][2], pl[mf][kf][2]);
                pack_hilo(s[mf][n1][2], s[mf][n1][3], ph[mf][kf][3], pl[mf][kf][3]);
            }
        }

#pragma unroll
        for (int kf = 0; kf < 4; kf++) {
            unsigned vh[4][4], vl[4][4];
#pragma unroll
            for (int g4 = 0; g4 < 4; g4++) {
                const unsigned bo = (unsigned)(((g4 * 16 + lrB) * 72 + kf * 16 + lcB) * 2);
                ldm4(vh[g4], uVh + bo);
                ldm4(vl[g4], uVl + bo);
            }
#pragma unroll
            for (int nf = 0; nf < 8; nf++) {
                const unsigned* bh = &vh[nf >> 1][(nf & 1) * 2];
                const unsigned* bl = &vl[nf >> 1][(nf & 1) * 2];
#pragma unroll
                for (int mf = 0; mf < 2; mf++) {
                    MMA_BF16(o[mf][nf], ph[mf][kf], bh);
                    MMA_BF16(o[mf][nf], pl[mf][kf], bh);
                    MMA_BF16(o[mf][nf], ph[mf][kf], bl);
                }
            }
        }
        __syncthreads();
    }

#pragma unroll
    for (int mf = 0; mf < 2; mf++) {
        const float inv0 = 1.0f / lrow[mf][0];
        const float inv1 = 1.0f / lrow[mf][1];
        const int r0 = q0 + rb0 + mf * 16 + g;
#pragma unroll
        for (int nf = 0; nf < 8; nf++) {
            const int col = h * 64 + nf * 8 + tg * 2;
            *reinterpret_cast<float2*>(out + (size_t)(r0 * 2 + b) * DMODEL + col) =
                make_float2(o[mf][nf][0] * inv0, o[mf][nf][1] * inv0);
            *reinterpret_cast<float2*>(out + (size_t)((r0 + 8) * 2 + b) * DMODEL + col) =
                make_float2(o[mf][nf][2] * inv1, o[mf][nf][3] * inv1);
        }
    }
}

// ---------------------------------------------------------------------------
extern "C" void kernel_launch(void* const* d_in, const int* in_sizes, int n_in,
                              void* d_out, int out_size) {
    const float* x = (const float*)d_in[0];
    const float* w = (const float*)d_in[1];
    if (n_in >= 2 && in_sizes[0] == E3 * DMODEL && in_sizes[1] == NROWS * DMODEL) {
        const float* t = x; x = w; w = t;
    }
    float* out = (float*)d_out;

    static bool attr_set = false;
    if (!attr_set) {
        cudaFuncSetAttribute(attn_tc, cudaFuncAttributeMaxDynamicSharedMemorySize,
                             ATTN_SMEM_BYTES);
        cudaFuncSetAttribute(qkv_gemm_tc, cudaFuncAttributeMaxDynamicSharedMemorySize,
                             QKV_SMEM);
        attr_set = true;
    }

    split_x<<<(NROWS * DMODEL / 4) / 256, 256>>>(x);
    split_w<<<(E3 * DMODEL / 4) / 256, 256>>>(w);
    qkv_gemm_tc<<<dim3(E3 / 128, NROWS / 128), 256, QKV_SMEM>>>();
    prep_qk<<<(NROWS * NHEADS * 2 * 16) / 256, 256>>>();
    prep_v<<<dim3(L_SEQ / 64, NHEADS, BATCH), 128>>>();
    attn_tc<<<dim3(L_SEQ / 128, NHEADS, BATCH), 128, ATTN_SMEM_BYTES>>>(out);
}